// round 1
// baseline (speedup 1.0000x reference)
#include <cuda_runtime.h>

#define NN 100000
#define EE 800000

// ---------------- scratch (device globals; no allocation allowed) ----------------
__device__ float g_h0[(size_t)NN * 128];
__device__ float g_sum_m[(size_t)NN * 128];
__device__ float g_sum_g[(size_t)NN * 128];
__device__ float g_pos[NN];
__device__ float g_cntm[NN];
__device__ float g_cntg[NN];
__device__ float g_hcat[(size_t)NN * 256];

__device__ __forceinline__ float leaky(float x) { return x > 0.f ? x : 0.1f * x; }

// ---------------- K0: zero accumulators ----------------
__global__ void k_zero(int n) {
    int i = blockIdx.x * blockDim.x + threadIdx.x;
    int tot = n * 32;  // n*128 floats / 4
    if (i < tot) {
        ((float4*)g_sum_m)[i] = make_float4(0.f, 0.f, 0.f, 0.f);
        ((float4*)g_sum_g)[i] = make_float4(0.f, 0.f, 0.f, 0.f);
    }
    if (i < n) { g_pos[i] = 0.f; g_cntm[i] = 0.f; g_cntg[i] = 0.f; }
}

// ---------------- K1: h0 = mlp_pi(pi_feat)  (4 -> 64 leaky -> 128) ----------------
__global__ void __launch_bounds__(256) k_pi(
    const float* __restrict__ pi_feat,
    const float* __restrict__ w1, const float* __restrict__ b1,
    const float* __restrict__ w2, const float* __restrict__ b2, int n)
{
    __shared__ float s_w1[256];
    __shared__ float s_b1[64];
    __shared__ float s_w2[8192];
    __shared__ float s_b2[128];
    for (int i = threadIdx.x; i < 256; i += blockDim.x) s_w1[i] = w1[i];
    for (int i = threadIdx.x; i < 64; i += blockDim.x) s_b1[i] = b1[i];
    for (int i = threadIdx.x; i < 8192; i += blockDim.x) s_w2[i] = w2[i];
    for (int i = threadIdx.x; i < 128; i += blockDim.x) s_b2[i] = b2[i];
    __syncthreads();

    int nd = blockIdx.x * blockDim.x + threadIdx.x;
    if (nd >= n) return;

    float4 pf = __ldg((const float4*)pi_feat + nd);
    float hid[64];
#pragma unroll
    for (int o = 0; o < 64; o++) {
        float v = s_b1[o] + pf.x * s_w1[o] + pf.y * s_w1[64 + o]
                + pf.z * s_w1[128 + o] + pf.w * s_w1[192 + o];
        hid[o] = leaky(v);
    }
    float* orow = g_h0 + (size_t)nd * 128;
#pragma unroll 1
    for (int j = 0; j < 128; j += 4) {
        float4 acc = *(const float4*)(s_b2 + j);
#pragma unroll
        for (int k = 0; k < 64; k++) {
            float4 w = *(const float4*)(s_w2 + k * 128 + j);
            acc.x += hid[k] * w.x; acc.y += hid[k] * w.y;
            acc.z += hid[k] * w.z; acc.w += hid[k] * w.w;
        }
        *(float4*)(orow + j) = acc;
    }
}

// ---------------- K2: edge gather + vectorized reduction ----------------
template <bool MODULE>
__global__ void __launch_bounds__(256) k_edges(
    const int* __restrict__ src, const int* __restrict__ dst,
    const float* __restrict__ bitpos, int E)
{
    float* sum = MODULE ? g_sum_m : g_sum_g;
    float* cnt = MODULE ? g_cntm : g_cntg;
    int lane = threadIdx.x & 31;
    int warp = (blockIdx.x * blockDim.x + threadIdx.x) >> 5;
    int nw = (gridDim.x * blockDim.x) >> 5;
    for (int e = warp; e < E; e += nw) {
        int s = __ldg(src + e);
        int d = __ldg(dst + e);
        float4 v = __ldg((const float4*)(g_h0 + (size_t)s * 128) + lane);
        float* p = sum + (size_t)d * 128 + lane * 4;
        asm volatile("red.global.add.v4.f32 [%0], {%1,%2,%3,%4};"
                     :: "l"(p), "f"(v.x), "f"(v.y), "f"(v.z), "f"(v.w) : "memory");
        if (lane == 0) {
            atomicAdd(cnt + d, 1.0f);
            if (MODULE) atomicAdd(g_pos + d, __ldg(bitpos + e));
        }
    }
}

// ---------------- K3: fused node MLP (branch-select) + global MLP -> hcat ----------
// smem float offsets
#define O_NMW1 0       // 193*64 = 12352
#define O_NMB1 12352   // 64
#define O_NMW2 12416   // 8192
#define O_NMB2 20608   // 128
#define O_NGW1 20736   // 192*64 = 12288
#define O_NGB1 33024   // 64
#define O_NGW2 33088   // 8192
#define O_NGB2 41280   // 128
#define O_GW1  41408   // 64
#define O_GB1  41472   // 64
#define O_GW2  41536   // 8192
#define O_GB2  49728   // 128
#define K3_SMEM 49856  // floats -> 199424 bytes

__global__ void __launch_bounds__(256) k_node(
    const float* __restrict__ feat, const float* __restrict__ level,
    const int* __restrict__ is_po, const int* __restrict__ is_module,
    const float* __restrict__ nm_w1, const float* __restrict__ nm_b1,
    const float* __restrict__ nm_w2, const float* __restrict__ nm_b2,
    const float* __restrict__ ng_w1, const float* __restrict__ ng_b1,
    const float* __restrict__ ng_w2, const float* __restrict__ ng_b2,
    const float* __restrict__ gw1, const float* __restrict__ gb1,
    const float* __restrict__ gw2, const float* __restrict__ gb2,
    int n)
{
    extern __shared__ float sm[];
    {
        int t = threadIdx.x, bs = blockDim.x;
        for (int i = t; i < 12352; i += bs) sm[O_NMW1 + i] = nm_w1[i];
        for (int i = t; i < 64;    i += bs) sm[O_NMB1 + i] = nm_b1[i];
        for (int i = t; i < 8192;  i += bs) sm[O_NMW2 + i] = nm_w2[i];
        for (int i = t; i < 128;   i += bs) sm[O_NMB2 + i] = nm_b2[i];
        for (int i = t; i < 12288; i += bs) sm[O_NGW1 + i] = ng_w1[i];
        for (int i = t; i < 64;    i += bs) sm[O_NGB1 + i] = ng_b1[i];
        for (int i = t; i < 8192;  i += bs) sm[O_NGW2 + i] = ng_w2[i];
        for (int i = t; i < 128;   i += bs) sm[O_NGB2 + i] = ng_b2[i];
        for (int i = t; i < 64;    i += bs) sm[O_GW1 + i] = gw1[i];
        for (int i = t; i < 64;    i += bs) sm[O_GB1 + i] = gb1[i];
        for (int i = t; i < 8192;  i += bs) sm[O_GW2 + i] = gw2[i];
        for (int i = t; i < 128;   i += bs) sm[O_GB2 + i] = gb2[i];
    }
    __syncthreads();

    int nd = blockIdx.x * blockDim.x + threadIdx.x;
    if (nd >= n) return;

    bool mod = (is_module[nd] == 1);
    float cnt = mod ? g_cntm[nd] : g_cntg[nd];
    float inv = 1.0f / fmaxf(cnt, 1.0f);
    const float4* srow = (const float4*)((mod ? g_sum_m : g_sum_g) + (size_t)nd * 128);
    const float* w1 = sm + (mod ? O_NMW1 : O_NGW1);
    const float* b1 = sm + (mod ? O_NMB1 : O_NGB1);
    const float* w2 = sm + (mod ? O_NMW2 : O_NGW2);
    const float* b2 = sm + (mod ? O_NMB2 : O_NGB2);

    float hid[64];
#pragma unroll
    for (int o = 0; o < 64; o++) hid[o] = b1[o];

    // neighbor mean (128 inputs)
#pragma unroll 1
    for (int k4 = 0; k4 < 32; k4++) {
        float4 v4 = __ldg(srow + k4);
        float xv[4] = {v4.x * inv, v4.y * inv, v4.z * inv, v4.w * inv};
        const float* wr = w1 + k4 * 4 * 64;
#pragma unroll
        for (int i = 0; i < 4; i++) {
            float x = xv[i];
            const float* w = wr + i * 64;
#pragma unroll
            for (int o = 0; o < 64; o += 4) {
                float4 ww = *(const float4*)(w + o);
                hid[o]     += x * ww.x;
                hid[o + 1] += x * ww.y;
                hid[o + 2] += x * ww.z;
                hid[o + 3] += x * ww.w;
            }
        }
    }
    // pos term (module path only; input index 128)
    if (mod) {
        float pos = g_pos[nd] * inv;
        const float* w = w1 + 128 * 64;
#pragma unroll
        for (int o = 0; o < 64; o += 4) {
            float4 ww = *(const float4*)(w + o);
            hid[o]     += pos * ww.x;
            hid[o + 1] += pos * ww.y;
            hid[o + 2] += pos * ww.z;
            hid[o + 3] += pos * ww.w;
        }
    }
    // feat (64 inputs; starts at row 129 for module, 128 for gate)
    {
        const float4* frow = (const float4*)(feat + (size_t)nd * 64);
        const float* w1f = w1 + (mod ? 129 * 64 : 128 * 64);
#pragma unroll 1
        for (int k4 = 0; k4 < 16; k4++) {
            float4 v4 = __ldg(frow + k4);
            float xv[4] = {v4.x, v4.y, v4.z, v4.w};
            const float* wr = w1f + k4 * 4 * 64;
#pragma unroll
            for (int i = 0; i < 4; i++) {
                float x = xv[i];
                const float* w = wr + i * 64;
#pragma unroll
                for (int o = 0; o < 64; o += 4) {
                    float4 ww = *(const float4*)(w + o);
                    hid[o]     += x * ww.x;
                    hid[o + 1] += x * ww.y;
                    hid[o + 2] += x * ww.z;
                    hid[o + 3] += x * ww.w;
                }
            }
        }
    }
#pragma unroll
    for (int o = 0; o < 64; o++) hid[o] = leaky(hid[o]);

    // h = hid @ w2_sel + b2_sel, optional ReLU (non-PO), write hcat[:,0:128]
    bool keep = (is_po[nd] != 1);
    float* orow = g_hcat + (size_t)nd * 256;
#pragma unroll 1
    for (int j = 0; j < 128; j += 4) {
        float4 acc = *(const float4*)(b2 + j);
#pragma unroll
        for (int k = 0; k < 64; k++) {
            float4 w = *(const float4*)(w2 + k * 128 + j);
            acc.x += hid[k] * w.x; acc.y += hid[k] * w.y;
            acc.z += hid[k] * w.z; acc.w += hid[k] * w.w;
        }
        if (keep) {
            acc.x = fmaxf(acc.x, 0.f); acc.y = fmaxf(acc.y, 0.f);
            acc.z = fmaxf(acc.z, 0.f); acc.w = fmaxf(acc.w, 0.f);
        }
        *(float4*)(orow + j) = acc;
    }

    // hg = mlp_global(level), write hcat[:,128:256]
    float lv = __ldg(level + nd);
#pragma unroll
    for (int o = 0; o < 64; o++) hid[o] = leaky(lv * sm[O_GW1 + o] + sm[O_GB1 + o]);
#pragma unroll 1
    for (int j = 0; j < 128; j += 4) {
        float4 acc = *(const float4*)(sm + O_GB2 + j);
#pragma unroll
        for (int k = 0; k < 64; k++) {
            float4 w = *(const float4*)(sm + O_GW2 + k * 128 + j);
            acc.x += hid[k] * w.x; acc.y += hid[k] * w.y;
            acc.z += hid[k] * w.z; acc.w += hid[k] * w.w;
        }
        *(float4*)(orow + 128 + j) = acc;
    }
}

// ---------------- K4: readout  out = mlp_out(hcat)  (256 -> 128 leaky -> 1) --------
#define K4_SMEM (32768 + 128 + 128)  // floats -> 132096 bytes
__global__ void __launch_bounds__(256) k_out(
    const float* __restrict__ o_w1, const float* __restrict__ o_b1,
    const float* __restrict__ o_w2, const float* __restrict__ o_b2,
    float* __restrict__ out, int n)
{
    extern __shared__ float sm[];
    for (int i = threadIdx.x; i < 32768; i += blockDim.x) sm[i] = o_w1[i];
    for (int i = threadIdx.x; i < 128; i += blockDim.x) {
        sm[32768 + i] = o_b1[i];
        sm[32896 + i] = o_w2[i];
    }
    __syncthreads();

    int nd = blockIdx.x * blockDim.x + threadIdx.x;
    if (nd >= n) return;

    float acc[128];
#pragma unroll
    for (int j = 0; j < 128; j++) acc[j] = sm[32768 + j];

    const float4* xr = (const float4*)(g_hcat + (size_t)nd * 256);
#pragma unroll 1
    for (int k4 = 0; k4 < 64; k4++) {
        float4 v4 = __ldg(xr + k4);
        float xv[4] = {v4.x, v4.y, v4.z, v4.w};
        const float* wr = sm + k4 * 4 * 128;
#pragma unroll
        for (int i = 0; i < 4; i++) {
            float x = xv[i];
            const float* w = wr + i * 128;
#pragma unroll
            for (int j = 0; j < 128; j += 4) {
                float4 ww = *(const float4*)(w + j);
                acc[j]     += x * ww.x;
                acc[j + 1] += x * ww.y;
                acc[j + 2] += x * ww.z;
                acc[j + 3] += x * ww.w;
            }
        }
    }
    float r = __ldg(o_b2);
#pragma unroll
    for (int j = 0; j < 128; j++) r += leaky(acc[j]) * sm[32896 + j];
    out[nd] = r;
}

// ---------------- host launch ----------------
extern "C" void kernel_launch(void* const* d_in, const int* in_sizes, int n_in,
                              void* d_out, int out_size)
{
    const float* feat    = (const float*)d_in[0];
    const float* pi_feat = (const float*)d_in[1];
    const float* level   = (const float*)d_in[2];
    const float* bitpos  = (const float*)d_in[3];

    const int *is_po, *is_module, *src_m, *dst_m, *src_g, *dst_g;
    const float *pi_w1, *pi_b1, *pi_w2, *pi_b2;
    const float *nm_w1, *nm_b1, *nm_w2, *nm_b2;
    const float *ng_w1, *ng_b1, *ng_w2, *ng_b2;
    const float *gw1, *gb1, *gw2, *gb2;
    const float *o_w1, *o_b1, *o_w2, *o_b2;

    // Disambiguate input ordering at runtime:
    // dict order has is_po (size N ~ 100000) at index 4;
    // reference-signature order has pi_w1 (size 256) at index 4.
    if (in_sizes[4] < 1000) {
        // signature order
        pi_w1 = (const float*)d_in[4];  pi_b1 = (const float*)d_in[5];
        pi_w2 = (const float*)d_in[6];  pi_b2 = (const float*)d_in[7];
        nm_w1 = (const float*)d_in[8];  nm_b1 = (const float*)d_in[9];
        nm_w2 = (const float*)d_in[10]; nm_b2 = (const float*)d_in[11];
        ng_w1 = (const float*)d_in[12]; ng_b1 = (const float*)d_in[13];
        ng_w2 = (const float*)d_in[14]; ng_b2 = (const float*)d_in[15];
        gw1 = (const float*)d_in[16];   gb1 = (const float*)d_in[17];
        gw2 = (const float*)d_in[18];   gb2 = (const float*)d_in[19];
        o_w1 = (const float*)d_in[20];  o_b1 = (const float*)d_in[21];
        o_w2 = (const float*)d_in[22];  o_b2 = (const float*)d_in[23];
        is_po = (const int*)d_in[24];   is_module = (const int*)d_in[25];
        src_m = (const int*)d_in[26];   dst_m = (const int*)d_in[27];
        src_g = (const int*)d_in[28];   dst_g = (const int*)d_in[29];
    } else {
        // setup_inputs dict order
        is_po = (const int*)d_in[4];    is_module = (const int*)d_in[5];
        src_m = (const int*)d_in[6];    dst_m = (const int*)d_in[7];
        src_g = (const int*)d_in[8];    dst_g = (const int*)d_in[9];
        pi_w1 = (const float*)d_in[10]; pi_b1 = (const float*)d_in[11];
        pi_w2 = (const float*)d_in[12]; pi_b2 = (const float*)d_in[13];
        nm_w1 = (const float*)d_in[14]; nm_b1 = (const float*)d_in[15];
        nm_w2 = (const float*)d_in[16]; nm_b2 = (const float*)d_in[17];
        ng_w1 = (const float*)d_in[18]; ng_b1 = (const float*)d_in[19];
        ng_w2 = (const float*)d_in[20]; ng_b2 = (const float*)d_in[21];
        gw1 = (const float*)d_in[22];   gb1 = (const float*)d_in[23];
        gw2 = (const float*)d_in[24];   gb2 = (const float*)d_in[25];
        o_w1 = (const float*)d_in[26];  o_b1 = (const float*)d_in[27];
        o_w2 = (const float*)d_in[28];  o_b2 = (const float*)d_in[29];
    }

    int n = in_sizes[2];               // level has N elements
    int E = in_sizes[0] / 64 == n ? (in_sizes[4] < 1000 ? in_sizes[26] : in_sizes[6])
                                  : (in_sizes[4] < 1000 ? in_sizes[26] : in_sizes[6]);

    cudaFuncSetAttribute(k_node, cudaFuncAttributeMaxDynamicSharedMemorySize, K3_SMEM * 4);
    cudaFuncSetAttribute(k_out, cudaFuncAttributeMaxDynamicSharedMemorySize, K4_SMEM * 4);

    int zb = (n * 32 + 255) / 256;
    k_zero<<<zb, 256>>>(n);

    k_pi<<<(n + 255) / 256, 256>>>(pi_feat, pi_w1, pi_b1, pi_w2, pi_b2, n);

    long long totw = (long long)E * 32;
    int eb = (int)((totw + 255) / 256);
    k_edges<true><<<eb, 256>>>(src_m, dst_m, bitpos, E);
    k_edges<false><<<eb, 256>>>(src_g, dst_g, bitpos, E);

    k_node<<<(n + 255) / 256, 256, K3_SMEM * 4>>>(
        feat, level, is_po, is_module,
        nm_w1, nm_b1, nm_w2, nm_b2,
        ng_w1, ng_b1, ng_w2, ng_b2,
        gw1, gb1, gw2, gb2, n);

    k_out<<<(n + 255) / 256, 256, K4_SMEM * 4>>>(
        o_w1, o_b1, o_w2, o_b2, (float*)d_out, n);
}

// round 2
// speedup vs baseline: 1.2525x; 1.2525x over previous
#include <cuda_runtime.h>

#define NN 100000

typedef unsigned long long u64;

// ---------------- scratch (device globals) ----------------
__device__ float g_h0[(size_t)NN * 128];
__device__ float g_sum_m[(size_t)NN * 128];
__device__ float g_sum_g[(size_t)NN * 128];
__device__ float g_pos[NN];
__device__ float g_cntm[NN];
__device__ float g_cntg[NN];
__device__ float g_hcat[(size_t)NN * 256];
__device__ int   g_nm, g_ng;
__device__ int   g_perm_m[NN];
__device__ int   g_perm_g[NN];

__device__ __forceinline__ float leaky(float x) { return x > 0.f ? x : 0.1f * x; }

// ---- packed f32x2 helpers ----
__device__ __forceinline__ u64 pack2(float x, float y) {
    u64 r; asm("mov.b64 %0,{%1,%2};" : "=l"(r) : "f"(x), "f"(y)); return r;
}
__device__ __forceinline__ void unpack2(u64 v, float& x, float& y) {
    asm("mov.b64 {%0,%1},%2;" : "=f"(x), "=f"(y) : "l"(v));
}
__device__ __forceinline__ void fma2(u64& acc, u64 a, u64 b) {
    asm("fma.rn.f32x2 %0,%1,%2,%0;" : "+l"(acc) : "l"(a), "l"(b));
}

// one input feature into 64-wide hidden accumulator (32 packed pairs)
__device__ __forceinline__ void l1in(u64* h2, float x, const float* w) {
    u64 xx = pack2(x, x);
    const ulonglong2* wp = (const ulonglong2*)w;
#pragma unroll
    for (int i = 0; i < 16; i++) {
        ulonglong2 ww = wp[i];
        fma2(h2[2 * i], xx, ww.x);
        fma2(h2[2 * i + 1], xx, ww.y);
    }
}

// 64 -> 32-output chunk of a 64x128 layer. h2: 32 packed hidden pairs (already leaky'd)
__device__ __forceinline__ void layer2_chunk(
    const u64* h2, const float* w2, const float* b2, int j0, u64* acc)
{
    const u64* bp = (const u64*)(b2 + j0);
#pragma unroll
    for (int i = 0; i < 16; i++) acc[i] = bp[i];
#pragma unroll 8
    for (int kk = 0; kk < 32; kk++) {
        float a, b; unpack2(h2[kk], a, b);
        u64 xa = pack2(a, a), xb = pack2(b, b);
        const ulonglong2* wa = (const ulonglong2*)(w2 + (2 * kk) * 128 + j0);
        const ulonglong2* wb = (const ulonglong2*)(w2 + (2 * kk + 1) * 128 + j0);
#pragma unroll
        for (int i = 0; i < 8; i++) {
            ulonglong2 w = wa[i];
            fma2(acc[2 * i], xa, w.x); fma2(acc[2 * i + 1], xa, w.y);
        }
#pragma unroll
        for (int i = 0; i < 8; i++) {
            ulonglong2 w = wb[i];
            fma2(acc[2 * i], xb, w.x); fma2(acc[2 * i + 1], xb, w.y);
        }
    }
}

// apply leaky to packed pairs in place
__device__ __forceinline__ void leaky_pack(u64* h2) {
#pragma unroll
    for (int i = 0; i < 32; i++) {
        float a, b; unpack2(h2[i], a, b);
        h2[i] = pack2(leaky(a), leaky(b));
    }
}

// ---------------- K0: zero accumulators ----------------
__global__ void k_zero(int n) {
    int i = blockIdx.x * blockDim.x + threadIdx.x;
    int tot = n * 32;
    if (i < tot) {
        ((float4*)g_sum_m)[i] = make_float4(0.f, 0.f, 0.f, 0.f);
        ((float4*)g_sum_g)[i] = make_float4(0.f, 0.f, 0.f, 0.f);
    }
    if (i < n) { g_pos[i] = 0.f; g_cntm[i] = 0.f; g_cntg[i] = 0.f; }
    if (i == 0) { g_nm = 0; g_ng = 0; }
}

// ---------------- K1: partition nodes by type ----------------
__global__ void k_part(const int* __restrict__ is_module, int n) {
    int i = blockIdx.x * blockDim.x + threadIdx.x;
    bool valid = i < n;
    bool m = valid && (is_module[i] == 1);
    bool g = valid && !m;
    unsigned bm = __ballot_sync(0xffffffffu, m);
    unsigned bg = __ballot_sync(0xffffffffu, g);
    int lane = threadIdx.x & 31;
    int base_m = 0, base_g = 0;
    if (lane == 0) {
        base_m = atomicAdd(&g_nm, __popc(bm));
        base_g = atomicAdd(&g_ng, __popc(bg));
    }
    base_m = __shfl_sync(0xffffffffu, base_m, 0);
    base_g = __shfl_sync(0xffffffffu, base_g, 0);
    unsigned lt = (1u << lane) - 1u;
    if (m) g_perm_m[base_m + __popc(bm & lt)] = i;
    if (g) g_perm_g[base_g + __popc(bg & lt)] = i;
}

// ---------------- K2: h0 = mlp_pi(pi_feat), hg = mlp_global(level) -> hcat[:,128:] ----
// smem float offsets: piw1 0(256) pib1 256(64) piw2 320(8192) pib2 8512(128)
//                     gw1 8640(64) gb1 8704(64) gw2 8768(8192) gb2 16960(128) tot 17088
#define PRE_SMEM (17088 * 4)
__global__ void __launch_bounds__(256) k_pre(
    const float* __restrict__ pi_feat, const float* __restrict__ level,
    const float* __restrict__ piw1, const float* __restrict__ pib1,
    const float* __restrict__ piw2, const float* __restrict__ pib2,
    const float* __restrict__ gw1, const float* __restrict__ gb1,
    const float* __restrict__ gw2, const float* __restrict__ gb2, int n)
{
    extern __shared__ float sm[];
    {
        int t = threadIdx.x;
        for (int i = t; i < 256; i += 256) sm[i] = piw1[i];
        for (int i = t; i < 64; i += 256) sm[256 + i] = pib1[i];
        for (int i = t; i < 8192; i += 256) sm[320 + i] = piw2[i];
        for (int i = t; i < 128; i += 256) sm[8512 + i] = pib2[i];
        for (int i = t; i < 64; i += 256) sm[8640 + i] = gw1[i];
        for (int i = t; i < 64; i += 256) sm[8704 + i] = gb1[i];
        for (int i = t; i < 8192; i += 256) sm[8768 + i] = gw2[i];
        for (int i = t; i < 128; i += 256) sm[16960 + i] = gb2[i];
    }
    __syncthreads();

    int nd = blockIdx.x * blockDim.x + threadIdx.x;
    if (nd >= n) return;

    // pi branch
    float4 pf = __ldg((const float4*)pi_feat + nd);
    u64 h2[32];
    {
        const u64* bp = (const u64*)(sm + 256);
#pragma unroll
        for (int i = 0; i < 32; i++) h2[i] = bp[i];
        l1in(h2, pf.x, sm + 0 * 64);
        l1in(h2, pf.y, sm + 1 * 64);
        l1in(h2, pf.z, sm + 2 * 64);
        l1in(h2, pf.w, sm + 3 * 64);
        leaky_pack(h2);
    }
    float* orow = g_h0 + (size_t)nd * 128;
    u64 acc[16];
#pragma unroll 1
    for (int c = 0; c < 4; c++) {
        layer2_chunk(h2, sm + 320, sm + 8512, c * 32, acc);
        u64* op = (u64*)(orow + c * 32);
#pragma unroll
        for (int i = 0; i < 16; i++) op[i] = acc[i];
    }

    // global branch
    float lv = __ldg(level + nd);
#pragma unroll
    for (int o = 0; o < 32; o++) {
        float a = leaky(lv * sm[8640 + 2 * o] + sm[8704 + 2 * o]);
        float b = leaky(lv * sm[8640 + 2 * o + 1] + sm[8704 + 2 * o + 1]);
        h2[o] = pack2(a, b);
    }
    float* grow = g_hcat + (size_t)nd * 256 + 128;
#pragma unroll 1
    for (int c = 0; c < 4; c++) {
        layer2_chunk(h2, sm + 8768, sm + 16960, c * 32, acc);
        u64* op = (u64*)(grow + c * 32);
#pragma unroll
        for (int i = 0; i < 16; i++) op[i] = acc[i];
    }
}

// ---------------- K3: edge gather + vectorized reduction (both edge sets) --------
__global__ void __launch_bounds__(256) k_edges_all(
    const int* __restrict__ src_m, const int* __restrict__ dst_m,
    const int* __restrict__ src_g, const int* __restrict__ dst_g,
    const float* __restrict__ bitpos, int Em, int Eg)
{
    int lane = threadIdx.x & 31;
    long long w = ((long long)blockIdx.x * blockDim.x + threadIdx.x) >> 5;
    if (w < Em) {
        int e = (int)w;
        int s = __ldg(src_m + e);
        int d = __ldg(dst_m + e);
        float4 v = __ldg((const float4*)(g_h0 + (size_t)s * 128) + lane);
        float* p = g_sum_m + (size_t)d * 128 + lane * 4;
        asm volatile("red.global.add.v4.f32 [%0], {%1,%2,%3,%4};"
                     :: "l"(p), "f"(v.x), "f"(v.y), "f"(v.z), "f"(v.w) : "memory");
        if (lane == 0) {
            atomicAdd(g_cntm + d, 1.0f);
            atomicAdd(g_pos + d, __ldg(bitpos + e));
        }
    } else {
        int e = (int)(w - Em);
        if (e >= Eg) return;
        int s = __ldg(src_g + e);
        int d = __ldg(dst_g + e);
        float4 v = __ldg((const float4*)(g_h0 + (size_t)s * 128) + lane);
        float* p = g_sum_g + (size_t)d * 128 + lane * 4;
        asm volatile("red.global.add.v4.f32 [%0], {%1,%2,%3,%4};"
                     :: "l"(p), "f"(v.x), "f"(v.y), "f"(v.z), "f"(v.w) : "memory");
        if (lane == 0) atomicAdd(g_cntg + d, 1.0f);
    }
}

// ---------------- K4: node MLP per type -> hcat[:,0:128] ----------------
// smem: w1 NIN*64 | b1 64 | w2 8192 | b2 128
template <bool MODULE>
__global__ void __launch_bounds__(256, 2) k_node(
    const float* __restrict__ feat, const int* __restrict__ is_po,
    const float* __restrict__ w1, const float* __restrict__ b1,
    const float* __restrict__ w2, const float* __restrict__ b2)
{
    constexpr int NIN = MODULE ? 193 : 192;
    int total = MODULE ? g_nm : g_ng;
    if ((int)(blockIdx.x * 256) >= total) return;

    extern __shared__ float sm[];
    float* s_w1 = sm;
    float* s_b1 = sm + NIN * 64;
    float* s_w2 = s_b1 + 64;
    float* s_b2 = s_w2 + 8192;
    {
        int t = threadIdx.x;
        for (int i = t; i < NIN * 64; i += 256) s_w1[i] = w1[i];
        for (int i = t; i < 64; i += 256) s_b1[i] = b1[i];
        for (int i = t; i < 8192; i += 256) s_w2[i] = w2[i];
        for (int i = t; i < 128; i += 256) s_b2[i] = b2[i];
    }
    __syncthreads();

    int t = blockIdx.x * 256 + threadIdx.x;
    if (t >= total) return;
    int nd = MODULE ? g_perm_m[t] : g_perm_g[t];

    float cnt = MODULE ? g_cntm[nd] : g_cntg[nd];
    float inv = 1.0f / fmaxf(cnt, 1.0f);
    const float4* srow = (const float4*)((MODULE ? g_sum_m : g_sum_g) + (size_t)nd * 128);

    u64 h2[32];
    {
        const u64* bp = (const u64*)s_b1;
#pragma unroll
        for (int i = 0; i < 32; i++) h2[i] = bp[i];
    }
    // neighbor mean (128 inputs)
#pragma unroll 2
    for (int k4 = 0; k4 < 32; k4++) {
        float4 v = __ldg(srow + k4);
        const float* wr = s_w1 + (k4 * 4) * 64;
        l1in(h2, v.x * inv, wr);
        l1in(h2, v.y * inv, wr + 64);
        l1in(h2, v.z * inv, wr + 128);
        l1in(h2, v.w * inv, wr + 192);
    }
    // pos (module only), then feat
    if (MODULE) {
        float pos = g_pos[nd] * inv;
        l1in(h2, pos, s_w1 + 128 * 64);
    }
    {
        const float4* frow = (const float4*)(feat + (size_t)nd * 64);
        const float* wf = s_w1 + (MODULE ? 129 : 128) * 64;
#pragma unroll 2
        for (int k4 = 0; k4 < 16; k4++) {
            float4 v = __ldg(frow + k4);
            const float* wr = wf + (k4 * 4) * 64;
            l1in(h2, v.x, wr);
            l1in(h2, v.y, wr + 64);
            l1in(h2, v.z, wr + 128);
            l1in(h2, v.w, wr + 192);
        }
    }
    leaky_pack(h2);

    bool keep = (__ldg(is_po + nd) != 1);
    float* orow = g_hcat + (size_t)nd * 256;
    u64 acc[16];
#pragma unroll 1
    for (int c = 0; c < 4; c++) {
        layer2_chunk(h2, s_w2, s_b2, c * 32, acc);
        u64* op = (u64*)(orow + c * 32);
#pragma unroll
        for (int i = 0; i < 16; i++) {
            float a, b; unpack2(acc[i], a, b);
            if (keep) { a = fmaxf(a, 0.f); b = fmaxf(b, 0.f); }
            op[i] = pack2(a, b);
        }
    }
}

// ---------------- K5: readout (256 -> 128 leaky -> 1) ----------------
// smem: w1 32768 | b1 128 | w2 128 -> 33024 floats
#define OUT_SMEM (33024 * 4)
__global__ void __launch_bounds__(256) k_out(
    const float* __restrict__ o_w1, const float* __restrict__ o_b1,
    const float* __restrict__ o_w2, const float* __restrict__ o_b2,
    float* __restrict__ out, int n)
{
    extern __shared__ float sm[];
    for (int i = threadIdx.x; i < 32768; i += 256) sm[i] = o_w1[i];
    for (int i = threadIdx.x; i < 128; i += 256) {
        sm[32768 + i] = o_b1[i];
        sm[32896 + i] = o_w2[i];
    }
    __syncthreads();

    int nd = blockIdx.x * blockDim.x + threadIdx.x;
    if (nd >= n) return;

    u64 acc[64];
    {
        const u64* bp = (const u64*)(sm + 32768);
#pragma unroll
        for (int i = 0; i < 64; i++) acc[i] = bp[i];
    }
    const float4* xr = (const float4*)(g_hcat + (size_t)nd * 256);
#pragma unroll 2
    for (int k4 = 0; k4 < 64; k4++) {
        float4 v = __ldg(xr + k4);
        float xv[4] = {v.x, v.y, v.z, v.w};
#pragma unroll
        for (int q = 0; q < 4; q++) {
            u64 xx = pack2(xv[q], xv[q]);
            const ulonglong2* wp = (const ulonglong2*)(sm + (k4 * 4 + q) * 128);
#pragma unroll
            for (int i = 0; i < 32; i++) {
                ulonglong2 w = wp[i];
                fma2(acc[2 * i], xx, w.x);
                fma2(acc[2 * i + 1], xx, w.y);
            }
        }
    }
    float r = __ldg(o_b2);
#pragma unroll
    for (int i = 0; i < 64; i++) {
        float a, b; unpack2(acc[i], a, b);
        r += leaky(a) * sm[32896 + 2 * i] + leaky(b) * sm[32896 + 2 * i + 1];
    }
    out[nd] = r;
}

// ---------------- host launch ----------------
extern "C" void kernel_launch(void* const* d_in, const int* in_sizes, int n_in,
                              void* d_out, int out_size)
{
    const float* feat    = (const float*)d_in[0];
    const float* pi_feat = (const float*)d_in[1];
    const float* level   = (const float*)d_in[2];
    const float* bitpos  = (const float*)d_in[3];

    const int *is_po, *is_module, *src_m, *dst_m, *src_g, *dst_g;
    const float *pi_w1, *pi_b1, *pi_w2, *pi_b2;
    const float *nm_w1, *nm_b1, *nm_w2, *nm_b2;
    const float *ng_w1, *ng_b1, *ng_w2, *ng_b2;
    const float *gw1, *gb1, *gw2, *gb2;
    const float *o_w1, *o_b1, *o_w2, *o_b2;
    int Em, Eg;

    if (in_sizes[4] < 1000) {
        // reference-signature order
        pi_w1 = (const float*)d_in[4];  pi_b1 = (const float*)d_in[5];
        pi_w2 = (const float*)d_in[6];  pi_b2 = (const float*)d_in[7];
        nm_w1 = (const float*)d_in[8];  nm_b1 = (const float*)d_in[9];
        nm_w2 = (const float*)d_in[10]; nm_b2 = (const float*)d_in[11];
        ng_w1 = (const float*)d_in[12]; ng_b1 = (const float*)d_in[13];
        ng_w2 = (const float*)d_in[14]; ng_b2 = (const float*)d_in[15];
        gw1 = (const float*)d_in[16];   gb1 = (const float*)d_in[17];
        gw2 = (const float*)d_in[18];   gb2 = (const float*)d_in[19];
        o_w1 = (const float*)d_in[20];  o_b1 = (const float*)d_in[21];
        o_w2 = (const float*)d_in[22];  o_b2 = (const float*)d_in[23];
        is_po = (const int*)d_in[24];   is_module = (const int*)d_in[25];
        src_m = (const int*)d_in[26];   dst_m = (const int*)d_in[27];
        src_g = (const int*)d_in[28];   dst_g = (const int*)d_in[29];
        Em = in_sizes[26]; Eg = in_sizes[28];
    } else {
        // setup_inputs dict order
        is_po = (const int*)d_in[4];    is_module = (const int*)d_in[5];
        src_m = (const int*)d_in[6];    dst_m = (const int*)d_in[7];
        src_g = (const int*)d_in[8];    dst_g = (const int*)d_in[9];
        pi_w1 = (const float*)d_in[10]; pi_b1 = (const float*)d_in[11];
        pi_w2 = (const float*)d_in[12]; pi_b2 = (const float*)d_in[13];
        nm_w1 = (const float*)d_in[14]; nm_b1 = (const float*)d_in[15];
        nm_w2 = (const float*)d_in[16]; nm_b2 = (const float*)d_in[17];
        ng_w1 = (const float*)d_in[18]; ng_b1 = (const float*)d_in[19];
        ng_w2 = (const float*)d_in[20]; ng_b2 = (const float*)d_in[21];
        gw1 = (const float*)d_in[22];   gb1 = (const float*)d_in[23];
        gw2 = (const float*)d_in[24];   gb2 = (const float*)d_in[25];
        o_w1 = (const float*)d_in[26];  o_b1 = (const float*)d_in[27];
        o_w2 = (const float*)d_in[28];  o_b2 = (const float*)d_in[29];
        Em = in_sizes[6]; Eg = in_sizes[8];
    }

    int n = in_sizes[2];  // level has N elements

    static int s_attr_done = 0;
    cudaFuncSetAttribute(k_pre, cudaFuncAttributeMaxDynamicSharedMemorySize, PRE_SMEM);
    cudaFuncSetAttribute(k_node<true>, cudaFuncAttributeMaxDynamicSharedMemorySize,
                         (193 * 64 + 64 + 8192 + 128) * 4);
    cudaFuncSetAttribute(k_node<false>, cudaFuncAttributeMaxDynamicSharedMemorySize,
                         (192 * 64 + 64 + 8192 + 128) * 4);
    cudaFuncSetAttribute(k_out, cudaFuncAttributeMaxDynamicSharedMemorySize, OUT_SMEM);
    (void)s_attr_done;

    int nb = (n + 255) / 256;

    k_zero<<<(n * 32 + 255) / 256, 256>>>(n);
    k_part<<<nb, 256>>>(is_module, n);
    k_pre<<<nb, 256, PRE_SMEM>>>(pi_feat, level, pi_w1, pi_b1, pi_w2, pi_b2,
                                 gw1, gb1, gw2, gb2, n);

    long long totw = (long long)(Em + Eg) * 32;
    int eb = (int)((totw + 255) / 256);
    k_edges_all<<<eb, 256>>>(src_m, dst_m, src_g, dst_g, bitpos, Em, Eg);

    k_node<true><<<nb, 256, (193 * 64 + 64 + 8192 + 128) * 4>>>(
        feat, is_po, nm_w1, nm_b1, nm_w2, nm_b2);
    k_node<false><<<nb, 256, (192 * 64 + 64 + 8192 + 128) * 4>>>(
        feat, is_po, ng_w1, ng_b1, ng_w2, ng_b2);

    k_out<<<nb, 256, OUT_SMEM>>>(o_w1, o_b1, o_w2, o_b2, (float*)d_out, n);
}

// round 3
// speedup vs baseline: 1.4247x; 1.1375x over previous
#include <cuda_runtime.h>

#define NN 100000

typedef unsigned long long u64;

// ---------------- scratch (device globals) ----------------
__device__ float g_h0[(size_t)NN * 128];
__device__ float g_sum_m[(size_t)NN * 128];
__device__ float g_sum_g[(size_t)NN * 128];
__device__ float g_pos[NN];
__device__ float g_cntm[NN];
__device__ float g_cntg[NN];
__device__ float g_hcat[(size_t)NN * 256];
__device__ int   g_nm, g_ng;
__device__ int   g_perm_m[NN];
__device__ int   g_perm_g[NN];

__device__ __forceinline__ float leaky(float x) { return x > 0.f ? x : 0.1f * x; }

// ---- packed f32x2 helpers ----
__device__ __forceinline__ u64 pack2(float x, float y) {
    u64 r; asm("mov.b64 %0,{%1,%2};" : "=l"(r) : "f"(x), "f"(y)); return r;
}
__device__ __forceinline__ void unpack2(u64 v, float& x, float& y) {
    asm("mov.b64 {%0,%1},%2;" : "=f"(x), "=f"(y) : "l"(v));
}
__device__ __forceinline__ void fma2(u64& acc, u64 a, u64 b) {
    asm("fma.rn.f32x2 %0,%1,%2,%0;" : "+l"(acc) : "l"(a), "l"(b));
}

// one input feature into 64-wide hidden accumulator (32 packed pairs)
__device__ __forceinline__ void l1in(u64* h2, float x, const float* w) {
    u64 xx = pack2(x, x);
    const ulonglong2* wp = (const ulonglong2*)w;
#pragma unroll
    for (int i = 0; i < 16; i++) {
        ulonglong2 ww = wp[i];
        fma2(h2[2 * i], xx, ww.x);
        fma2(h2[2 * i + 1], xx, ww.y);
    }
}

// 64 -> 32-output chunk of a 64x128 layer. h2: 32 packed hidden pairs (already leaky'd)
__device__ __forceinline__ void layer2_chunk(
    const u64* h2, const float* w2, const float* b2, int j0, u64* acc)
{
    const u64* bp = (const u64*)(b2 + j0);
#pragma unroll
    for (int i = 0; i < 16; i++) acc[i] = bp[i];
#pragma unroll 8
    for (int kk = 0; kk < 32; kk++) {
        float a, b; unpack2(h2[kk], a, b);
        u64 xa = pack2(a, a), xb = pack2(b, b);
        const ulonglong2* wa = (const ulonglong2*)(w2 + (2 * kk) * 128 + j0);
        const ulonglong2* wb = (const ulonglong2*)(w2 + (2 * kk + 1) * 128 + j0);
#pragma unroll
        for (int i = 0; i < 8; i++) {
            ulonglong2 w = wa[i];
            fma2(acc[2 * i], xa, w.x); fma2(acc[2 * i + 1], xa, w.y);
        }
#pragma unroll
        for (int i = 0; i < 8; i++) {
            ulonglong2 w = wb[i];
            fma2(acc[2 * i], xb, w.x); fma2(acc[2 * i + 1], xb, w.y);
        }
    }
}

__device__ __forceinline__ void leaky_pack(u64* h2) {
#pragma unroll
    for (int i = 0; i < 32; i++) {
        float a, b; unpack2(h2[i], a, b);
        h2[i] = pack2(leaky(a), leaky(b));
    }
}

// ---------------- K0: zero accumulators ----------------
__global__ void k_zero(int n) {
    int i = blockIdx.x * blockDim.x + threadIdx.x;
    int tot = n * 32;
    if (i < tot) {
        ((float4*)g_sum_m)[i] = make_float4(0.f, 0.f, 0.f, 0.f);
        ((float4*)g_sum_g)[i] = make_float4(0.f, 0.f, 0.f, 0.f);
    }
    if (i < n) { g_pos[i] = 0.f; g_cntm[i] = 0.f; g_cntg[i] = 0.f; }
    if (i == 0) { g_nm = 0; g_ng = 0; }
}

// ---------------- K1: partition nodes by type ----------------
__global__ void k_part(const int* __restrict__ is_module, int n) {
    int i = blockIdx.x * blockDim.x + threadIdx.x;
    bool valid = i < n;
    bool m = valid && (is_module[i] == 1);
    bool g = valid && !m;
    unsigned bm = __ballot_sync(0xffffffffu, m);
    unsigned bg = __ballot_sync(0xffffffffu, g);
    int lane = threadIdx.x & 31;
    int base_m = 0, base_g = 0;
    if (lane == 0) {
        base_m = atomicAdd(&g_nm, __popc(bm));
        base_g = atomicAdd(&g_ng, __popc(bg));
    }
    base_m = __shfl_sync(0xffffffffu, base_m, 0);
    base_g = __shfl_sync(0xffffffffu, base_g, 0);
    unsigned lt = (1u << lane) - 1u;
    if (m) g_perm_m[base_m + __popc(bm & lt)] = i;
    if (g) g_perm_g[base_g + __popc(bg & lt)] = i;
}

// ---------------- K2: h0 = mlp_pi(pi_feat), hg = mlp_global(level) -> hcat[:,128:]
// also out[nd] = o_b2[0]
// smem: piw1 0(256) pib1 256(64) piw2 320(8192) pib2 8512(128)
//       gw1 8640(64) gb1 8704(64) gw2 8768(8192) gb2 16960(128) tot 17088
#define PRE_SMEM (17088 * 4)
__global__ void __launch_bounds__(256) k_pre(
    const float* __restrict__ pi_feat, const float* __restrict__ level,
    const float* __restrict__ piw1, const float* __restrict__ pib1,
    const float* __restrict__ piw2, const float* __restrict__ pib2,
    const float* __restrict__ gw1, const float* __restrict__ gb1,
    const float* __restrict__ gw2, const float* __restrict__ gb2,
    const float* __restrict__ o_b2, float* __restrict__ out, int n)
{
    extern __shared__ float sm[];
    {
        int t = threadIdx.x;
        for (int i = t; i < 256; i += 256) sm[i] = piw1[i];
        for (int i = t; i < 64; i += 256) sm[256 + i] = pib1[i];
        for (int i = t; i < 8192; i += 256) sm[320 + i] = piw2[i];
        for (int i = t; i < 128; i += 256) sm[8512 + i] = pib2[i];
        for (int i = t; i < 64; i += 256) sm[8640 + i] = gw1[i];
        for (int i = t; i < 64; i += 256) sm[8704 + i] = gb1[i];
        for (int i = t; i < 8192; i += 256) sm[8768 + i] = gw2[i];
        for (int i = t; i < 128; i += 256) sm[16960 + i] = gb2[i];
    }
    __syncthreads();

    int nd = blockIdx.x * blockDim.x + threadIdx.x;
    if (nd >= n) return;

    out[nd] = __ldg(o_b2);  // seed readout accumulator

    // pi branch
    float4 pf = __ldg((const float4*)pi_feat + nd);
    u64 h2[32];
    {
        const u64* bp = (const u64*)(sm + 256);
#pragma unroll
        for (int i = 0; i < 32; i++) h2[i] = bp[i];
        l1in(h2, pf.x, sm + 0 * 64);
        l1in(h2, pf.y, sm + 1 * 64);
        l1in(h2, pf.z, sm + 2 * 64);
        l1in(h2, pf.w, sm + 3 * 64);
        leaky_pack(h2);
    }
    float* orow = g_h0 + (size_t)nd * 128;
    u64 acc[16];
#pragma unroll 1
    for (int c = 0; c < 4; c++) {
        layer2_chunk(h2, sm + 320, sm + 8512, c * 32, acc);
        u64* op = (u64*)(orow + c * 32);
#pragma unroll
        for (int i = 0; i < 16; i++) op[i] = acc[i];
    }

    // global branch
    float lv = __ldg(level + nd);
#pragma unroll
    for (int o = 0; o < 32; o++) {
        float a = leaky(lv * sm[8640 + 2 * o] + sm[8704 + 2 * o]);
        float b = leaky(lv * sm[8640 + 2 * o + 1] + sm[8704 + 2 * o + 1]);
        h2[o] = pack2(a, b);
    }
    float* grow = g_hcat + (size_t)nd * 256 + 128;
#pragma unroll 1
    for (int c = 0; c < 4; c++) {
        layer2_chunk(h2, sm + 8768, sm + 16960, c * 32, acc);
        u64* op = (u64*)(grow + c * 32);
#pragma unroll
        for (int i = 0; i < 16; i++) op[i] = acc[i];
    }
}

// ---------------- K3: edge gather + reduction, 4 edges per warp for MLP ----------
#define EPW 4
__global__ void __launch_bounds__(256) k_edges_all(
    const int* __restrict__ src_m, const int* __restrict__ dst_m,
    const int* __restrict__ src_g, const int* __restrict__ dst_g,
    const float* __restrict__ bitpos, int Em, int Eg)
{
    int lane = threadIdx.x & 31;
    long long wid = ((long long)blockIdx.x * blockDim.x + threadIdx.x) >> 5;
    long long base = wid * EPW;
    long long Etot = (long long)Em + Eg;
    if (base >= Etot) return;
    int cnt = (int)(Etot - base < EPW ? Etot - base : EPW);

    int s[EPW], d[EPW];
    bool ism[EPW];
#pragma unroll
    for (int i = 0; i < EPW; i++) {
        if (i < cnt) {
            long long e = base + i;
            if (e < Em) {
                ism[i] = true;
                s[i] = __ldg(src_m + e);
                d[i] = __ldg(dst_m + e);
            } else {
                ism[i] = false;
                s[i] = __ldg(src_g + (e - Em));
                d[i] = __ldg(dst_g + (e - Em));
            }
        }
    }
    float4 v[EPW];
#pragma unroll
    for (int i = 0; i < EPW; i++)
        if (i < cnt) v[i] = __ldg((const float4*)(g_h0 + (size_t)s[i] * 128) + lane);
#pragma unroll
    for (int i = 0; i < EPW; i++) {
        if (i < cnt) {
            float* p = (ism[i] ? g_sum_m : g_sum_g) + (size_t)d[i] * 128 + lane * 4;
            asm volatile("red.global.add.v4.f32 [%0], {%1,%2,%3,%4};"
                         :: "l"(p), "f"(v[i].x), "f"(v[i].y), "f"(v[i].z), "f"(v[i].w)
                         : "memory");
            if (lane == 0) {
                if (ism[i]) {
                    atomicAdd(g_cntm + d[i], 1.0f);
                    atomicAdd(g_pos + d[i], __ldg(bitpos + base + i));
                } else {
                    atomicAdd(g_cntg + d[i], 1.0f);
                }
            }
        }
    }
}

// ---------------- K4: node MLP, both types in one launch -> hcat[:,0:128] --------
// smem: w1 193*64 | b1 64 | w2 8192 | b2 128 = 20736 floats (82944 B)
#define NODE_SMEM (20736 * 4)
__global__ void __launch_bounds__(256) k_node_all(
    const float* __restrict__ feat, const int* __restrict__ is_po,
    const float* __restrict__ nm_w1, const float* __restrict__ nm_b1,
    const float* __restrict__ nm_w2, const float* __restrict__ nm_b2,
    const float* __restrict__ ng_w1, const float* __restrict__ ng_b1,
    const float* __restrict__ ng_w2, const float* __restrict__ ng_b2)
{
    int nbm = (g_nm + 255) >> 8;
    bool MOD = (int)blockIdx.x < nbm;
    int tbase = (MOD ? blockIdx.x : blockIdx.x - nbm) * 256;
    int total = MOD ? g_nm : g_ng;
    if (tbase >= total) return;

    int NIN = MOD ? 193 : 192;
    const float* w1 = MOD ? nm_w1 : ng_w1;
    const float* b1 = MOD ? nm_b1 : ng_b1;
    const float* w2 = MOD ? nm_w2 : ng_w2;
    const float* b2 = MOD ? nm_b2 : ng_b2;

    extern __shared__ float sm[];
    float* s_w1 = sm;
    float* s_b1 = sm + NIN * 64;
    float* s_w2 = s_b1 + 64;
    float* s_b2 = s_w2 + 8192;
    {
        int t = threadIdx.x;
        for (int i = t; i < NIN * 64; i += 256) s_w1[i] = w1[i];
        for (int i = t; i < 64; i += 256) s_b1[i] = b1[i];
        for (int i = t; i < 8192; i += 256) s_w2[i] = w2[i];
        for (int i = t; i < 128; i += 256) s_b2[i] = b2[i];
    }
    __syncthreads();

    int t = tbase + threadIdx.x;
    if (t >= total) return;
    int nd = MOD ? g_perm_m[t] : g_perm_g[t];

    float cnt = MOD ? g_cntm[nd] : g_cntg[nd];
    float inv = 1.0f / fmaxf(cnt, 1.0f);
    const float4* srow = (const float4*)((MOD ? g_sum_m : g_sum_g) + (size_t)nd * 128);

    u64 h2[32];
    {
        const u64* bp = (const u64*)s_b1;
#pragma unroll
        for (int i = 0; i < 32; i++) h2[i] = bp[i];
    }
    // neighbor mean (128 inputs)
#pragma unroll 2
    for (int k4 = 0; k4 < 32; k4++) {
        float4 v = __ldg(srow + k4);
        const float* wr = s_w1 + (k4 * 4) * 64;
        l1in(h2, v.x * inv, wr);
        l1in(h2, v.y * inv, wr + 64);
        l1in(h2, v.z * inv, wr + 128);
        l1in(h2, v.w * inv, wr + 192);
    }
    // pos (module only), then feat
    if (MOD) {
        float pos = g_pos[nd] * inv;
        l1in(h2, pos, s_w1 + 128 * 64);
    }
    {
        const float4* frow = (const float4*)(feat + (size_t)nd * 64);
        const float* wf = s_w1 + (MOD ? 129 : 128) * 64;
#pragma unroll 2
        for (int k4 = 0; k4 < 16; k4++) {
            float4 v = __ldg(frow + k4);
            const float* wr = wf + (k4 * 4) * 64;
            l1in(h2, v.x, wr);
            l1in(h2, v.y, wr + 64);
            l1in(h2, v.z, wr + 128);
            l1in(h2, v.w, wr + 192);
        }
    }
    leaky_pack(h2);

    bool keep = (__ldg(is_po + nd) != 1);
    float* orow = g_hcat + (size_t)nd * 256;
    u64 acc[16];
#pragma unroll 1
    for (int c = 0; c < 4; c++) {
        layer2_chunk(h2, s_w2, s_b2, c * 32, acc);
        u64* op = (u64*)(orow + c * 32);
#pragma unroll
        for (int i = 0; i < 16; i++) {
            float a, b; unpack2(acc[i], a, b);
            if (keep) { a = fmaxf(a, 0.f); b = fmaxf(b, 0.f); }
            op[i] = pack2(a, b);
        }
    }
}

// ---------------- K5: readout, split by hidden-half  (256 -> 64 leaky -> partial)
// smem: w1half 256*64=16384 | b1half 64 | w2half 64 -> 16512 floats (66048 B)
#define OUT_SMEM (16512 * 4)
__global__ void __launch_bounds__(256) k_out(
    const float* __restrict__ o_w1, const float* __restrict__ o_b1,
    const float* __restrict__ o_w2, float* __restrict__ out, int n)
{
    int half = blockIdx.x & 1;
    int nb = blockIdx.x >> 1;

    extern __shared__ float sm[];
    for (int i = threadIdx.x; i < 16384; i += 256) {
        int row = i >> 6, col = i & 63;
        sm[i] = o_w1[row * 128 + half * 64 + col];
    }
    for (int i = threadIdx.x; i < 64; i += 256) {
        sm[16384 + i] = o_b1[half * 64 + i];
        sm[16448 + i] = o_w2[half * 64 + i];
    }
    __syncthreads();

    int nd = nb * 256 + threadIdx.x;
    if (nd >= n) return;

    u64 acc[32];
    {
        const u64* bp = (const u64*)(sm + 16384);
#pragma unroll
        for (int i = 0; i < 32; i++) acc[i] = bp[i];
    }
    const float4* xr = (const float4*)(g_hcat + (size_t)nd * 256);
#pragma unroll 2
    for (int k4 = 0; k4 < 64; k4++) {
        float4 v = __ldg(xr + k4);
        float xv[4] = {v.x, v.y, v.z, v.w};
#pragma unroll
        for (int q = 0; q < 4; q++) {
            u64 xx = pack2(xv[q], xv[q]);
            const ulonglong2* wp = (const ulonglong2*)(sm + (k4 * 4 + q) * 64);
#pragma unroll
            for (int i = 0; i < 16; i++) {
                ulonglong2 w = wp[i];
                fma2(acc[2 * i], xx, w.x);
                fma2(acc[2 * i + 1], xx, w.y);
            }
        }
    }
    float r = 0.f;
#pragma unroll
    for (int i = 0; i < 32; i++) {
        float a, b; unpack2(acc[i], a, b);
        r += leaky(a) * sm[16448 + 2 * i] + leaky(b) * sm[16448 + 2 * i + 1];
    }
    atomicAdd(out + nd, r);
}

// ---------------- host launch ----------------
extern "C" void kernel_launch(void* const* d_in, const int* in_sizes, int n_in,
                              void* d_out, int out_size)
{
    const float* feat    = (const float*)d_in[0];
    const float* pi_feat = (const float*)d_in[1];
    const float* level   = (const float*)d_in[2];
    const float* bitpos  = (const float*)d_in[3];

    const int *is_po, *is_module, *src_m, *dst_m, *src_g, *dst_g;
    const float *pi_w1, *pi_b1, *pi_w2, *pi_b2;
    const float *nm_w1, *nm_b1, *nm_w2, *nm_b2;
    const float *ng_w1, *ng_b1, *ng_w2, *ng_b2;
    const float *gw1, *gb1, *gw2, *gb2;
    const float *o_w1, *o_b1, *o_w2, *o_b2;
    int Em, Eg;

    if (in_sizes[4] < 1000) {
        // reference-signature order
        pi_w1 = (const float*)d_in[4];  pi_b1 = (const float*)d_in[5];
        pi_w2 = (const float*)d_in[6];  pi_b2 = (const float*)d_in[7];
        nm_w1 = (const float*)d_in[8];  nm_b1 = (const float*)d_in[9];
        nm_w2 = (const float*)d_in[10]; nm_b2 = (const float*)d_in[11];
        ng_w1 = (const float*)d_in[12]; ng_b1 = (const float*)d_in[13];
        ng_w2 = (const float*)d_in[14]; ng_b2 = (const float*)d_in[15];
        gw1 = (const float*)d_in[16];   gb1 = (const float*)d_in[17];
        gw2 = (const float*)d_in[18];   gb2 = (const float*)d_in[19];
        o_w1 = (const float*)d_in[20];  o_b1 = (const float*)d_in[21];
        o_w2 = (const float*)d_in[22];  o_b2 = (const float*)d_in[23];
        is_po = (const int*)d_in[24];   is_module = (const int*)d_in[25];
        src_m = (const int*)d_in[26];   dst_m = (const int*)d_in[27];
        src_g = (const int*)d_in[28];   dst_g = (const int*)d_in[29];
        Em = in_sizes[26]; Eg = in_sizes[28];
    } else {
        // setup_inputs dict order
        is_po = (const int*)d_in[4];    is_module = (const int*)d_in[5];
        src_m = (const int*)d_in[6];    dst_m = (const int*)d_in[7];
        src_g = (const int*)d_in[8];    dst_g = (const int*)d_in[9];
        pi_w1 = (const float*)d_in[10]; pi_b1 = (const float*)d_in[11];
        pi_w2 = (const float*)d_in[12]; pi_b2 = (const float*)d_in[13];
        nm_w1 = (const float*)d_in[14]; nm_b1 = (const float*)d_in[15];
        nm_w2 = (const float*)d_in[16]; nm_b2 = (const float*)d_in[17];
        ng_w1 = (const float*)d_in[18]; ng_b1 = (const float*)d_in[19];
        ng_w2 = (const float*)d_in[20]; ng_b2 = (const float*)d_in[21];
        gw1 = (const float*)d_in[22];   gb1 = (const float*)d_in[23];
        gw2 = (const float*)d_in[24];   gb2 = (const float*)d_in[25];
        o_w1 = (const float*)d_in[26];  o_b1 = (const float*)d_in[27];
        o_w2 = (const float*)d_in[28];  o_b2 = (const float*)d_in[29];
        Em = in_sizes[6]; Eg = in_sizes[8];
    }

    int n = in_sizes[2];  // level has N elements

    cudaFuncSetAttribute(k_pre, cudaFuncAttributeMaxDynamicSharedMemorySize, PRE_SMEM);
    cudaFuncSetAttribute(k_node_all, cudaFuncAttributeMaxDynamicSharedMemorySize, NODE_SMEM);
    cudaFuncSetAttribute(k_out, cudaFuncAttributeMaxDynamicSharedMemorySize, OUT_SMEM);

    int nb = (n + 255) / 256;

    k_zero<<<(n * 32 + 255) / 256, 256>>>(n);
    k_part<<<nb, 256>>>(is_module, n);
    k_pre<<<nb, 256, PRE_SMEM>>>(pi_feat, level, pi_w1, pi_b1, pi_w2, pi_b2,
                                 gw1, gb1, gw2, gb2, o_b2, (float*)d_out, n);

    long long Etot = (long long)Em + Eg;
    long long warps = (Etot + EPW - 1) / EPW;
    int eb = (int)((warps * 32 + 255) / 256);
    k_edges_all<<<eb, 256>>>(src_m, dst_m, src_g, dst_g, bitpos, Em, Eg);

    k_node_all<<<nb + 1, 256, NODE_SMEM>>>(
        feat, is_po,
        nm_w1, nm_b1, nm_w2, nm_b2,
        ng_w1, ng_b1, ng_w2, ng_b2);

    k_out<<<nb * 2, 256, OUT_SMEM>>>(o_w1, o_b1, o_w2, (float*)d_out, n);
}

// round 4
// speedup vs baseline: 1.8407x; 1.2921x over previous
#include <cuda_runtime.h>

#define NN 100000

typedef unsigned long long u64;

// ---------------- scratch (device globals) ----------------
__device__ float g_h0[(size_t)NN * 128];
__device__ float g_sum_m[(size_t)NN * 128];
__device__ float g_sum_g[(size_t)NN * 128];
__device__ float g_pos[NN];
__device__ float g_cntm[NN];
__device__ float g_cntg[NN];
__device__ float g_h[(size_t)NN * 128];
__device__ int   g_nm, g_ng;
__device__ int   g_perm_m[NN];
__device__ int   g_perm_g[NN];
// piecewise-linear table for the global-branch contribution to mlp_out hidden
__device__ float g_M[64 * 128];
__device__ float g_C[128];
__device__ float g_A[65 * 128];
__device__ float g_B[65 * 128];
__device__ float g_knots[64];

__device__ __forceinline__ float leaky(float x) { return x > 0.f ? x : 0.1f * x; }

// ---- packed f32x2 helpers ----
__device__ __forceinline__ u64 pack2(float x, float y) {
    u64 r; asm("mov.b64 %0,{%1,%2};" : "=l"(r) : "f"(x), "f"(y)); return r;
}
__device__ __forceinline__ void unpack2(u64 v, float& x, float& y) {
    asm("mov.b64 {%0,%1},%2;" : "=f"(x), "=f"(y) : "l"(v));
}
__device__ __forceinline__ void fma2(u64& acc, u64 a, u64 b) {
    asm("fma.rn.f32x2 %0,%1,%2,%0;" : "+l"(acc) : "l"(a), "l"(b));
}

// one input feature into 64-wide accumulator (32 packed pairs)
__device__ __forceinline__ void l1in(u64* h2, float x, const float* w) {
    u64 xx = pack2(x, x);
    const ulonglong2* wp = (const ulonglong2*)w;
#pragma unroll
    for (int i = 0; i < 16; i++) {
        ulonglong2 ww = wp[i];
        fma2(h2[2 * i], xx, ww.x);
        fma2(h2[2 * i + 1], xx, ww.y);
    }
}

// 64 -> 32-output chunk of a 64x128 layer. h2: 32 packed hidden pairs (already activated)
__device__ __forceinline__ void layer2_chunk(
    const u64* h2, const float* w2, const float* b2, int j0, u64* acc)
{
    const u64* bp = (const u64*)(b2 + j0);
#pragma unroll
    for (int i = 0; i < 16; i++) acc[i] = bp[i];
#pragma unroll 8
    for (int kk = 0; kk < 32; kk++) {
        float a, b; unpack2(h2[kk], a, b);
        u64 xa = pack2(a, a), xb = pack2(b, b);
        const ulonglong2* wa = (const ulonglong2*)(w2 + (2 * kk) * 128 + j0);
        const ulonglong2* wb = (const ulonglong2*)(w2 + (2 * kk + 1) * 128 + j0);
#pragma unroll
        for (int i = 0; i < 8; i++) {
            ulonglong2 w = wa[i];
            fma2(acc[2 * i], xa, w.x); fma2(acc[2 * i + 1], xa, w.y);
        }
#pragma unroll
        for (int i = 0; i < 8; i++) {
            ulonglong2 w = wb[i];
            fma2(acc[2 * i], xb, w.x); fma2(acc[2 * i + 1], xb, w.y);
        }
    }
}

__device__ __forceinline__ void leaky_pack(u64* h2) {
#pragma unroll
    for (int i = 0; i < 32; i++) {
        float a, b; unpack2(h2[i], a, b);
        h2[i] = pack2(leaky(a), leaky(b));
    }
}

// ---------------- K0: zero small scalars + counters ----------------
__global__ void k_zero_small(int n) {
    int i = blockIdx.x * blockDim.x + threadIdx.x;
    if (i < n) { g_pos[i] = 0.f; g_cntm[i] = 0.f; g_cntg[i] = 0.f; }
    if (i == 0) { g_nm = 0; g_ng = 0; }
}

// ---------------- K1: partition nodes by type ----------------
__global__ void k_part(const int* __restrict__ is_module, int n) {
    int i = blockIdx.x * blockDim.x + threadIdx.x;
    bool valid = i < n;
    bool m = valid && (is_module[i] == 1);
    bool g = valid && !m;
    unsigned bm = __ballot_sync(0xffffffffu, m);
    unsigned bg = __ballot_sync(0xffffffffu, g);
    int lane = threadIdx.x & 31;
    int base_m = 0, base_g = 0;
    if (lane == 0) {
        base_m = atomicAdd(&g_nm, __popc(bm));
        base_g = atomicAdd(&g_ng, __popc(bg));
    }
    base_m = __shfl_sync(0xffffffffu, base_m, 0);
    base_g = __shfl_sync(0xffffffffu, base_g, 0);
    unsigned lt = (1u << lane) - 1u;
    if (m) g_perm_m[base_m + __popc(bm & lt)] = i;
    if (g) g_perm_g[base_g + __popc(bg & lt)] = i;
}

// ---------------- KT1: M = gw2 @ o_w1_gate  (64x128), C = gb2 @ o_w1_gate ---------
__global__ void k_m(const float* __restrict__ gw2, const float* __restrict__ gb2,
                    const float* __restrict__ o_w1)
{
    int k = blockIdx.x;   // 0..64 (64 => C row)
    int j = threadIdx.x;  // 0..127
    float acc = 0.f;
    if (k < 64) {
#pragma unroll 8
        for (int c = 0; c < 128; c++)
            acc += __ldg(gw2 + k * 128 + c) * __ldg(o_w1 + (size_t)(128 + c) * 128 + j);
        g_M[k * 128 + j] = acc;
    } else {
#pragma unroll 8
        for (int c = 0; c < 128; c++)
            acc += __ldg(gb2 + c) * __ldg(o_w1 + (size_t)(128 + c) * 128 + j);
        g_C[j] = acc;
    }
}

// ---------------- KT2: per-segment (A,B); block = segment ----------------
__global__ void k_table(const float* __restrict__ gw1, const float* __restrict__ gb1)
{
    __shared__ float s_t[64], s_w[64], s_b[64];
    __shared__ int s_pos[64];
    int j = threadIdx.x;   // 0..127
    int s = blockIdx.x;    // 0..64
    if (j < 64) {
        float w = gw1[j], b = gb1[j];
        s_w[j] = w; s_b[j] = b;
        s_t[j] = (w != 0.f) ? (-b / w) : 3.0e38f;
    }
    __syncthreads();
    if (j < 64) {
        float t = s_t[j];
        int r = 0;
        for (int i = 0; i < 64; i++) {
            float ti = s_t[i];
            if (ti < t || (ti == t && i < j)) r++;
        }
        s_pos[j] = r;
    }
    __syncthreads();
    if (s == 0 && j < 64) g_knots[s_pos[j]] = s_t[j];

    float A = 0.f, B = g_C[j];
#pragma unroll 8
    for (int k = 0; k < 64; k++) {
        float w = s_w[k], b = s_b[k];
        bool positive = (w > 0.f) ? (s > s_pos[k])
                       : (w < 0.f) ? (s <= s_pos[k])
                       : (b > 0.f);
        float sc = positive ? 1.0f : 0.1f;
        float m = g_M[k * 128 + j];
        A += sc * w * m;
        B += sc * b * m;
    }
    g_A[s * 128 + j] = A;
    g_B[s * 128 + j] = B;
}

// ---------------- K2: h0 = mlp_pi(pi_feat); seed out with o_b2 ----------------
// smem: piw1 0(256) pib1 256(64) piw2 320(8192) pib2 8512(128) tot 8640
#define PRE_SMEM (8640 * 4)
__global__ void __launch_bounds__(256) k_pre(
    const float* __restrict__ pi_feat,
    const float* __restrict__ piw1, const float* __restrict__ pib1,
    const float* __restrict__ piw2, const float* __restrict__ pib2,
    const float* __restrict__ o_b2, float* __restrict__ out, int n)
{
    extern __shared__ float sm[];
    {
        int t = threadIdx.x;
        for (int i = t; i < 256; i += 256) sm[i] = piw1[i];
        for (int i = t; i < 64; i += 256) sm[256 + i] = pib1[i];
        for (int i = t; i < 8192; i += 256) sm[320 + i] = piw2[i];
        for (int i = t; i < 128; i += 256) sm[8512 + i] = pib2[i];
    }
    __syncthreads();

    int nd = blockIdx.x * blockDim.x + threadIdx.x;
    if (nd >= n) return;

    out[nd] = __ldg(o_b2);  // seed readout accumulator

    float4 pf = __ldg((const float4*)pi_feat + nd);
    u64 h2[32];
    {
        const u64* bp = (const u64*)(sm + 256);
#pragma unroll
        for (int i = 0; i < 32; i++) h2[i] = bp[i];
        l1in(h2, pf.x, sm + 0 * 64);
        l1in(h2, pf.y, sm + 1 * 64);
        l1in(h2, pf.z, sm + 2 * 64);
        l1in(h2, pf.w, sm + 3 * 64);
        leaky_pack(h2);
    }
    float* orow = g_h0 + (size_t)nd * 128;
    u64 acc[16];
#pragma unroll 1
    for (int c = 0; c < 4; c++) {
        layer2_chunk(h2, sm + 320, sm + 8512, c * 32, acc);
        u64* op = (u64*)(orow + c * 32);
#pragma unroll
        for (int i = 0; i < 16; i++) op[i] = acc[i];
    }
}

// ---------------- K3: edge gather + reduction, 4 edges per warp ----------
#define EPW 4
__global__ void __launch_bounds__(256) k_edges_all(
    const int* __restrict__ src_m, const int* __restrict__ dst_m,
    const int* __restrict__ src_g, const int* __restrict__ dst_g,
    const float* __restrict__ bitpos, int Em, int Eg)
{
    int lane = threadIdx.x & 31;
    long long wid = ((long long)blockIdx.x * blockDim.x + threadIdx.x) >> 5;
    long long base = wid * EPW;
    long long Etot = (long long)Em + Eg;
    if (base >= Etot) return;
    int cnt = (int)(Etot - base < EPW ? Etot - base : EPW);

    int s[EPW], d[EPW];
    bool ism[EPW];
#pragma unroll
    for (int i = 0; i < EPW; i++) {
        if (i < cnt) {
            long long e = base + i;
            if (e < Em) {
                ism[i] = true;
                s[i] = __ldg(src_m + e);
                d[i] = __ldg(dst_m + e);
            } else {
                ism[i] = false;
                s[i] = __ldg(src_g + (e - Em));
                d[i] = __ldg(dst_g + (e - Em));
            }
        }
    }
    float4 v[EPW];
#pragma unroll
    for (int i = 0; i < EPW; i++)
        if (i < cnt) v[i] = __ldg((const float4*)(g_h0 + (size_t)s[i] * 128) + lane);
#pragma unroll
    for (int i = 0; i < EPW; i++) {
        if (i < cnt) {
            float* p = (ism[i] ? g_sum_m : g_sum_g) + (size_t)d[i] * 128 + lane * 4;
            asm volatile("red.global.add.v4.f32 [%0], {%1,%2,%3,%4};"
                         :: "l"(p), "f"(v[i].x), "f"(v[i].y), "f"(v[i].z), "f"(v[i].w)
                         : "memory");
            if (lane == 0) {
                if (ism[i]) {
                    atomicAdd(g_cntm + d[i], 1.0f);
                    atomicAdd(g_pos + d[i], __ldg(bitpos + base + i));
                } else {
                    atomicAdd(g_cntg + d[i], 1.0f);
                }
            }
        }
    }
}

// ---------------- K4: node MLP, both types in one launch -> g_h ----------
// smem: w1 193*64 | b1 64 | w2 8192 | b2 128 = 20736 floats (82944 B)
#define NODE_SMEM (20736 * 4)
__global__ void __launch_bounds__(256) k_node_all(
    const float* __restrict__ feat, const int* __restrict__ is_po,
    const float* __restrict__ nm_w1, const float* __restrict__ nm_b1,
    const float* __restrict__ nm_w2, const float* __restrict__ nm_b2,
    const float* __restrict__ ng_w1, const float* __restrict__ ng_b1,
    const float* __restrict__ ng_w2, const float* __restrict__ ng_b2)
{
    int nbm = (g_nm + 255) >> 8;
    bool MOD = (int)blockIdx.x < nbm;
    int tbase = (MOD ? blockIdx.x : blockIdx.x - nbm) * 256;
    int total = MOD ? g_nm : g_ng;
    if (tbase >= total) return;

    int NIN = MOD ? 193 : 192;
    const float* w1 = MOD ? nm_w1 : ng_w1;
    const float* b1 = MOD ? nm_b1 : ng_b1;
    const float* w2 = MOD ? nm_w2 : ng_w2;
    const float* b2 = MOD ? nm_b2 : ng_b2;

    extern __shared__ float sm[];
    float* s_w1 = sm;
    float* s_b1 = sm + NIN * 64;
    float* s_w2 = s_b1 + 64;
    float* s_b2 = s_w2 + 8192;
    {
        int t = threadIdx.x;
        for (int i = t; i < NIN * 64; i += 256) s_w1[i] = w1[i];
        for (int i = t; i < 64; i += 256) s_b1[i] = b1[i];
        for (int i = t; i < 8192; i += 256) s_w2[i] = w2[i];
        for (int i = t; i < 128; i += 256) s_b2[i] = b2[i];
    }
    __syncthreads();

    int t = tbase + threadIdx.x;
    if (t >= total) return;
    int nd = MOD ? g_perm_m[t] : g_perm_g[t];

    float cnt = MOD ? g_cntm[nd] : g_cntg[nd];
    float inv = 1.0f / fmaxf(cnt, 1.0f);
    const float4* srow = (const float4*)((MOD ? g_sum_m : g_sum_g) + (size_t)nd * 128);

    u64 h2[32];
    {
        const u64* bp = (const u64*)s_b1;
#pragma unroll
        for (int i = 0; i < 32; i++) h2[i] = bp[i];
    }
    // neighbor mean (128 inputs)
#pragma unroll 2
    for (int k4 = 0; k4 < 32; k4++) {
        float4 v = __ldg(srow + k4);
        const float* wr = s_w1 + (k4 * 4) * 64;
        l1in(h2, v.x * inv, wr);
        l1in(h2, v.y * inv, wr + 64);
        l1in(h2, v.z * inv, wr + 128);
        l1in(h2, v.w * inv, wr + 192);
    }
    if (MOD) {
        float pos = g_pos[nd] * inv;
        l1in(h2, pos, s_w1 + 128 * 64);
    }
    {
        const float4* frow = (const float4*)(feat + (size_t)nd * 64);
        const float* wf = s_w1 + (MOD ? 129 : 128) * 64;
#pragma unroll 2
        for (int k4 = 0; k4 < 16; k4++) {
            float4 v = __ldg(frow + k4);
            const float* wr = wf + (k4 * 4) * 64;
            l1in(h2, v.x, wr);
            l1in(h2, v.y, wr + 64);
            l1in(h2, v.z, wr + 128);
            l1in(h2, v.w, wr + 192);
        }
    }
    leaky_pack(h2);

    bool keep = (__ldg(is_po + nd) != 1);
    float* orow = g_h + (size_t)nd * 128;
    u64 acc[16];
#pragma unroll 1
    for (int c = 0; c < 4; c++) {
        layer2_chunk(h2, s_w2, s_b2, c * 32, acc);
        u64* op = (u64*)(orow + c * 32);
#pragma unroll
        for (int i = 0; i < 16; i++) {
            float a, b; unpack2(acc[i], a, b);
            if (keep) { a = fmaxf(a, 0.f); b = fmaxf(b, 0.f); }
            op[i] = pack2(a, b);
        }
    }
}

// ---------------- K5: readout, split by hidden-half (128 -> 64 + table -> partial)
// smem floats: w1h 0..8191 | A 8192 (65*66=4290) | B 12482 (4290) |
//              b1 16772(64) | w2 16836(64) | knots 16900(64) -> 16964 floats
#define SM_A 8192
#define SM_B 12482
#define SM_B1 16772
#define SM_W2 16836
#define SM_KN 16900
#define OUT_SMEM (16964 * 4)
__global__ void __launch_bounds__(256) k_out(
    const float* __restrict__ o_w1, const float* __restrict__ o_b1,
    const float* __restrict__ o_w2, const float* __restrict__ level,
    float* __restrict__ out, int n)
{
    int half = blockIdx.x & 1;
    int nb = blockIdx.x >> 1;

    extern __shared__ float sm[];
    for (int i = threadIdx.x; i < 8192; i += 256) {
        int row = i >> 6, col = i & 63;
        sm[i] = o_w1[row * 128 + half * 64 + col];
    }
    for (int i = threadIdx.x; i < 65 * 64; i += 256) {
        int seg = i >> 6, col = i & 63;
        sm[SM_A + seg * 66 + col] = g_A[seg * 128 + half * 64 + col];
        sm[SM_B + seg * 66 + col] = g_B[seg * 128 + half * 64 + col];
    }
    for (int i = threadIdx.x; i < 64; i += 256) {
        sm[SM_B1 + i] = o_b1[half * 64 + i];
        sm[SM_W2 + i] = o_w2[half * 64 + i];
        sm[SM_KN + i] = g_knots[i];
    }
    __syncthreads();

    int nd = nb * 256 + threadIdx.x;
    if (nd >= n) return;

    float lv = __ldg(level + nd);
    int s = 0;
#pragma unroll
    for (int k = 0; k < 64; k++) s += (sm[SM_KN + k] < lv) ? 1 : 0;

    u64 acc[32];
    {
        const float* Ar = sm + SM_A + s * 66;
        const float* Br = sm + SM_B + s * 66;
        const float* br = sm + SM_B1;
#pragma unroll
        for (int i = 0; i < 32; i++) {
            float a0 = fmaf(Ar[2 * i], lv, br[2 * i] + Br[2 * i]);
            float a1 = fmaf(Ar[2 * i + 1], lv, br[2 * i + 1] + Br[2 * i + 1]);
            acc[i] = pack2(a0, a1);
        }
    }
    const float4* xr = (const float4*)(g_h + (size_t)nd * 128);
#pragma unroll 2
    for (int k4 = 0; k4 < 32; k4++) {
        float4 v = __ldg(xr + k4);
        const float* wr = sm + (k4 * 4) * 64;
        l1in(acc, v.x, wr);
        l1in(acc, v.y, wr + 64);
        l1in(acc, v.z, wr + 128);
        l1in(acc, v.w, wr + 192);
    }
    float r = 0.f;
#pragma unroll
    for (int i = 0; i < 32; i++) {
        float a, b; unpack2(acc[i], a, b);
        r += leaky(a) * sm[SM_W2 + 2 * i] + leaky(b) * sm[SM_W2 + 2 * i + 1];
    }
    atomicAdd(out + nd, r);
}

// ---------------- host launch ----------------
extern "C" void kernel_launch(void* const* d_in, const int* in_sizes, int n_in,
                              void* d_out, int out_size)
{
    const float* feat    = (const float*)d_in[0];
    const float* pi_feat = (const float*)d_in[1];
    const float* level   = (const float*)d_in[2];
    const float* bitpos  = (const float*)d_in[3];

    const int *is_po, *is_module, *src_m, *dst_m, *src_g, *dst_g;
    const float *pi_w1, *pi_b1, *pi_w2, *pi_b2;
    const float *nm_w1, *nm_b1, *nm_w2, *nm_b2;
    const float *ng_w1, *ng_b1, *ng_w2, *ng_b2;
    const float *gw1, *gb1, *gw2, *gb2;
    const float *o_w1, *o_b1, *o_w2, *o_b2;
    int Em, Eg;

    if (in_sizes[4] < 1000) {
        // reference-signature order
        pi_w1 = (const float*)d_in[4];  pi_b1 = (const float*)d_in[5];
        pi_w2 = (const float*)d_in[6];  pi_b2 = (const float*)d_in[7];
        nm_w1 = (const float*)d_in[8];  nm_b1 = (const float*)d_in[9];
        nm_w2 = (const float*)d_in[10]; nm_b2 = (const float*)d_in[11];
        ng_w1 = (const float*)d_in[12]; ng_b1 = (const float*)d_in[13];
        ng_w2 = (const float*)d_in[14]; ng_b2 = (const float*)d_in[15];
        gw1 = (const float*)d_in[16];   gb1 = (const float*)d_in[17];
        gw2 = (const float*)d_in[18];   gb2 = (const float*)d_in[19];
        o_w1 = (const float*)d_in[20];  o_b1 = (const float*)d_in[21];
        o_w2 = (const float*)d_in[22];  o_b2 = (const float*)d_in[23];
        is_po = (const int*)d_in[24];   is_module = (const int*)d_in[25];
        src_m = (const int*)d_in[26];   dst_m = (const int*)d_in[27];
        src_g = (const int*)d_in[28];   dst_g = (const int*)d_in[29];
        Em = in_sizes[26]; Eg = in_sizes[28];
    } else {
        // setup_inputs dict order
        is_po = (const int*)d_in[4];    is_module = (const int*)d_in[5];
        src_m = (const int*)d_in[6];    dst_m = (const int*)d_in[7];
        src_g = (const int*)d_in[8];    dst_g = (const int*)d_in[9];
        pi_w1 = (const float*)d_in[10]; pi_b1 = (const float*)d_in[11];
        pi_w2 = (const float*)d_in[12]; pi_b2 = (const float*)d_in[13];
        nm_w1 = (const float*)d_in[14]; nm_b1 = (const float*)d_in[15];
        nm_w2 = (const float*)d_in[16]; nm_b2 = (const float*)d_in[17];
        ng_w1 = (const float*)d_in[18]; ng_b1 = (const float*)d_in[19];
        ng_w2 = (const float*)d_in[20]; ng_b2 = (const float*)d_in[21];
        gw1 = (const float*)d_in[22];   gb1 = (const float*)d_in[23];
        gw2 = (const float*)d_in[24];   gb2 = (const float*)d_in[25];
        o_w1 = (const float*)d_in[26];  o_b1 = (const float*)d_in[27];
        o_w2 = (const float*)d_in[28];  o_b2 = (const float*)d_in[29];
        Em = in_sizes[6]; Eg = in_sizes[8];
    }

    int n = in_sizes[2];  // level has N elements

    cudaFuncSetAttribute(k_pre, cudaFuncAttributeMaxDynamicSharedMemorySize, PRE_SMEM);
    cudaFuncSetAttribute(k_node_all, cudaFuncAttributeMaxDynamicSharedMemorySize, NODE_SMEM);
    cudaFuncSetAttribute(k_out, cudaFuncAttributeMaxDynamicSharedMemorySize, OUT_SMEM);

    int nb = (n + 255) / 256;

    // zero the big sum buffers with memsets (graph-capturable)
    void* p_sum_m = nullptr; void* p_sum_g = nullptr;
    cudaGetSymbolAddress(&p_sum_m, g_sum_m);
    cudaGetSymbolAddress(&p_sum_g, g_sum_g);
    cudaMemsetAsync(p_sum_m, 0, (size_t)n * 128 * 4);
    cudaMemsetAsync(p_sum_g, 0, (size_t)n * 128 * 4);

    k_zero_small<<<nb, 256>>>(n);
    k_part<<<nb, 256>>>(is_module, n);
    k_m<<<65, 128>>>(gw2, gb2, o_w1);
    k_table<<<65, 128>>>(gw1, gb1);

    k_pre<<<nb, 256, PRE_SMEM>>>(pi_feat, pi_w1, pi_b1, pi_w2, pi_b2,
                                 o_b2, (float*)d_out, n);

    long long Etot = (long long)Em + Eg;
    long long warps = (Etot + EPW - 1) / EPW;
    int eb = (int)((warps * 32 + 255) / 256);
    k_edges_all<<<eb, 256>>>(src_m, dst_m, src_g, dst_g, bitpos, Em, Eg);

    k_node_all<<<nb + 1, 256, NODE_SMEM>>>(
        feat, is_po,
        nm_w1, nm_b1, nm_w2, nm_b2,
        ng_w1, ng_b1, ng_w2, ng_b2);

    k_out<<<nb * 2, 256, OUT_SMEM>>>(o_w1, o_b1, o_w2, level, (float*)d_out, n);
}

// round 5
// speedup vs baseline: 2.1280x; 1.1561x over previous
#include <cuda_runtime.h>

#define NN 100000

typedef unsigned long long u64;

// ---------------- scratch (device globals) ----------------
__device__ float g_pm[(size_t)NN * 64];    // h0 projected through nm_w1 neigh block
__device__ float g_pg[(size_t)NN * 64];    // h0 projected through ng_w1 neigh block
__device__ float g_sum_m[(size_t)NN * 64];
__device__ float g_sum_g[(size_t)NN * 64];
__device__ float g_pos[NN];
__device__ float g_cntm[NN];
__device__ float g_cntg[NN];
__device__ float g_h[(size_t)NN * 128];
__device__ int   g_nm, g_ng;
__device__ int   g_perm_m[NN];
__device__ int   g_perm_g[NN];
// composed projection matrices: rows 0..63 = pi_w2 @ W_neigh, row 64 = pi_b2 @ W_neigh
__device__ float g_Cm[65 * 64];
__device__ float g_Cg[65 * 64];
// piecewise-linear table for the global-branch contribution to mlp_out hidden
__device__ float g_A[65 * 128];
__device__ float g_B[65 * 128];
__device__ float g_knots[64];

__device__ __forceinline__ float leaky(float x) { return x > 0.f ? x : 0.1f * x; }

// ---- packed f32x2 helpers ----
__device__ __forceinline__ u64 pack2(float x, float y) {
    u64 r; asm("mov.b64 %0,{%1,%2};" : "=l"(r) : "f"(x), "f"(y)); return r;
}
__device__ __forceinline__ void unpack2(u64 v, float& x, float& y) {
    asm("mov.b64 {%0,%1},%2;" : "=f"(x), "=f"(y) : "l"(v));
}
__device__ __forceinline__ void fma2(u64& acc, u64 a, u64 b) {
    asm("fma.rn.f32x2 %0,%1,%2,%0;" : "+l"(acc) : "l"(a), "l"(b));
}

// one input feature into 64-wide accumulator (32 packed pairs)
__device__ __forceinline__ void l1in(u64* h2, float x, const float* w) {
    u64 xx = pack2(x, x);
    const ulonglong2* wp = (const ulonglong2*)w;
#pragma unroll
    for (int i = 0; i < 16; i++) {
        ulonglong2 ww = wp[i];
        fma2(h2[2 * i], xx, ww.x);
        fma2(h2[2 * i + 1], xx, ww.y);
    }
}

// 64 inputs (32 packed, activated) -> 32 outputs at column j0 of a [64, STRIDE] matrix
template <int STRIDE>
__device__ __forceinline__ void layer2_chunk(
    const u64* h2, const float* w2, const float* b2, int j0, u64* acc)
{
    const u64* bp = (const u64*)(b2 + j0);
#pragma unroll
    for (int i = 0; i < 16; i++) acc[i] = bp[i];
#pragma unroll 8
    for (int kk = 0; kk < 32; kk++) {
        float a, b; unpack2(h2[kk], a, b);
        u64 xa = pack2(a, a), xb = pack2(b, b);
        const ulonglong2* wa = (const ulonglong2*)(w2 + (size_t)(2 * kk) * STRIDE + j0);
        const ulonglong2* wb = (const ulonglong2*)(w2 + (size_t)(2 * kk + 1) * STRIDE + j0);
#pragma unroll
        for (int i = 0; i < 8; i++) {
            ulonglong2 w = wa[i];
            fma2(acc[2 * i], xa, w.x); fma2(acc[2 * i + 1], xa, w.y);
        }
#pragma unroll
        for (int i = 0; i < 8; i++) {
            ulonglong2 w = wb[i];
            fma2(acc[2 * i], xb, w.x); fma2(acc[2 * i + 1], xb, w.y);
        }
    }
}

__device__ __forceinline__ void leaky_pack(u64* h2) {
#pragma unroll
    for (int i = 0; i < 32; i++) {
        float a, b; unpack2(h2[i], a, b);
        h2[i] = pack2(leaky(a), leaky(b));
    }
}

// ---------------- K0: zero small scalars + counters ----------------
__global__ void k_zero_small(int n) {
    int i = blockIdx.x * blockDim.x + threadIdx.x;
    if (i < n) { g_pos[i] = 0.f; g_cntm[i] = 0.f; g_cntg[i] = 0.f; }
    if (i == 0) { g_nm = 0; g_ng = 0; }
}

// ---------------- K1: partition nodes by type ----------------
__global__ void k_part(const int* __restrict__ is_module, int n) {
    int i = blockIdx.x * blockDim.x + threadIdx.x;
    bool valid = i < n;
    bool m = valid && (is_module[i] == 1);
    bool g = valid && !m;
    unsigned bm = __ballot_sync(0xffffffffu, m);
    unsigned bg = __ballot_sync(0xffffffffu, g);
    int lane = threadIdx.x & 31;
    int base_m = 0, base_g = 0;
    if (lane == 0) {
        base_m = atomicAdd(&g_nm, __popc(bm));
        base_g = atomicAdd(&g_ng, __popc(bg));
    }
    base_m = __shfl_sync(0xffffffffu, base_m, 0);
    base_g = __shfl_sync(0xffffffffu, base_g, 0);
    unsigned lt = (1u << lane) - 1u;
    if (m) g_perm_m[base_m + __popc(bm & lt)] = i;
    if (g) g_perm_g[base_g + __popc(bg & lt)] = i;
}

// ---------------- KC: composed projections Cm, Cg ----------------
// C[i][j] = sum_c piw2[i][c] * W[c][j]   (i<64);  row 64: pib2 @ W
__global__ void k_compose(
    const float* __restrict__ piw2, const float* __restrict__ pib2,
    const float* __restrict__ nmw1, const float* __restrict__ ngw1)
{
    int i = blockIdx.x;       // 0..64
    int gsel = blockIdx.y;    // 0=m 1=g
    int j = threadIdx.x;      // 0..63
    const float* W = gsel ? ngw1 : nmw1;   // [.,64], neigh rows 0..127
    const float* src = (i < 64) ? (piw2 + i * 128) : pib2;
    float acc = 0.f;
#pragma unroll 8
    for (int c = 0; c < 128; c++) acc += __ldg(src + c) * __ldg(W + c * 64 + j);
    (gsel ? g_Cg : g_Cm)[i * 64 + j] = acc;
}

// ---------------- KT: fused piecewise-linear table (A, B, knots) ----------------
__global__ void k_table2(
    const float* __restrict__ gw1, const float* __restrict__ gb1,
    const float* __restrict__ gw2, const float* __restrict__ gb2,
    const float* __restrict__ o_w1)
{
    __shared__ float s_t[64], s_w[64], s_b[64];
    __shared__ int s_pos[64];
    __shared__ float s_a[128], s_c[128];
    int j = threadIdx.x;   // 0..127
    int s = blockIdx.x;    // 0..64
    if (j < 64) {
        float w = gw1[j], b = gb1[j];
        s_w[j] = w; s_b[j] = b;
        s_t[j] = (w != 0.f) ? (-b / w) : 3.0e38f;
    }
    __syncthreads();
    if (j < 64) {
        float t = s_t[j];
        int r = 0;
        for (int i = 0; i < 64; i++) {
            float ti = s_t[i];
            if (ti < t || (ti == t && i < j)) r++;
        }
        s_pos[j] = r;
    }
    __syncthreads();
    if (s == 0 && j < 64) g_knots[s_pos[j]] = s_t[j];

    // a_c = sum_k sc_k*w_k*gw2[k][c];  c_c = sum_k sc_k*b_k*gw2[k][c] + gb2[c]
    {
        float a = 0.f, c = __ldg(gb2 + j);
#pragma unroll 8
        for (int k = 0; k < 64; k++) {
            float w = s_w[k], b = s_b[k];
            bool positive = (w > 0.f) ? (s > s_pos[k])
                           : (w < 0.f) ? (s <= s_pos[k])
                           : (b > 0.f);
            float sc = positive ? 1.0f : 0.1f;
            float gv = __ldg(gw2 + k * 128 + j);
            a += sc * w * gv;
            c += sc * b * gv;
        }
        s_a[j] = a; s_c[j] = c;
    }
    __syncthreads();

    float A = 0.f, B = 0.f;
#pragma unroll 8
    for (int c = 0; c < 128; c++) {
        float o = __ldg(o_w1 + (size_t)(128 + c) * 128 + j);
        A += s_a[c] * o;
        B += s_c[c] * o;
    }
    g_A[s * 128 + j] = A;
    g_B[s * 128 + j] = B;
}

// ---------------- K2: hid_pi -> p_m = hid@Cm, p_g = hid@Cg; seed out ----------------
// smem: piw1 0(256) pib1 256(64) Cm 320(4160) Cg 4480(4160) tot 8640
#define PRE_SMEM (8640 * 4)
__global__ void __launch_bounds__(256) k_pre(
    const float* __restrict__ pi_feat,
    const float* __restrict__ piw1, const float* __restrict__ pib1,
    const float* __restrict__ o_b2, float* __restrict__ out, int n)
{
    extern __shared__ float sm[];
    {
        int t = threadIdx.x;
        for (int i = t; i < 256; i += 256) sm[i] = piw1[i];
        for (int i = t; i < 64; i += 256) sm[256 + i] = pib1[i];
        for (int i = t; i < 4160; i += 256) sm[320 + i] = g_Cm[i];
        for (int i = t; i < 4160; i += 256) sm[4480 + i] = g_Cg[i];
    }
    __syncthreads();

    int nd = blockIdx.x * blockDim.x + threadIdx.x;
    if (nd >= n) return;

    out[nd] = __ldg(o_b2);  // seed readout accumulator

    float4 pf = __ldg((const float4*)pi_feat + nd);
    u64 h2[32];
    {
        const u64* bp = (const u64*)(sm + 256);
#pragma unroll
        for (int i = 0; i < 32; i++) h2[i] = bp[i];
        l1in(h2, pf.x, sm + 0 * 64);
        l1in(h2, pf.y, sm + 1 * 64);
        l1in(h2, pf.z, sm + 2 * 64);
        l1in(h2, pf.w, sm + 3 * 64);
        leaky_pack(h2);
    }
    u64 acc[16];
    float* pmrow = g_pm + (size_t)nd * 64;
#pragma unroll 1
    for (int c = 0; c < 2; c++) {
        layer2_chunk<64>(h2, sm + 320, sm + 320 + 64 * 64, c * 32, acc);
        u64* op = (u64*)(pmrow + c * 32);
#pragma unroll
        for (int i = 0; i < 16; i++) op[i] = acc[i];
    }
    float* pgrow = g_pg + (size_t)nd * 64;
#pragma unroll 1
    for (int c = 0; c < 2; c++) {
        layer2_chunk<64>(h2, sm + 4480, sm + 4480 + 64 * 64, c * 32, acc);
        u64* op = (u64*)(pgrow + c * 32);
#pragma unroll
        for (int i = 0; i < 16; i++) op[i] = acc[i];
    }
}

// ---------------- K3: edge gather + reduction, half-warp per edge, 64-dim ----------
#define EPHW 4
__global__ void __launch_bounds__(256) k_edges_all(
    const int* __restrict__ src_m, const int* __restrict__ dst_m,
    const int* __restrict__ src_g, const int* __restrict__ dst_g,
    const float* __restrict__ bitpos, int Em, int Eg)
{
    int l16 = threadIdx.x & 15;
    long long hw = ((long long)blockIdx.x * blockDim.x + threadIdx.x) >> 4;
    long long base = hw * EPHW;
    long long Etot = (long long)Em + Eg;
    if (base >= Etot) return;
    int cnt = (int)(Etot - base < EPHW ? Etot - base : EPHW);

    int s[EPHW], d[EPHW];
    bool ism[EPHW];
#pragma unroll
    for (int i = 0; i < EPHW; i++) {
        if (i < cnt) {
            long long e = base + i;
            if (e < Em) {
                ism[i] = true;
                s[i] = __ldg(src_m + e);
                d[i] = __ldg(dst_m + e);
            } else {
                ism[i] = false;
                s[i] = __ldg(src_g + (e - Em));
                d[i] = __ldg(dst_g + (e - Em));
            }
        }
    }
    float4 v[EPHW];
#pragma unroll
    for (int i = 0; i < EPHW; i++)
        if (i < cnt)
            v[i] = __ldg((const float4*)((ism[i] ? g_pm : g_pg) + (size_t)s[i] * 64) + l16);
#pragma unroll
    for (int i = 0; i < EPHW; i++) {
        if (i < cnt) {
            float* p = (ism[i] ? g_sum_m : g_sum_g) + (size_t)d[i] * 64 + l16 * 4;
            asm volatile("red.global.add.v4.f32 [%0], {%1,%2,%3,%4};"
                         :: "l"(p), "f"(v[i].x), "f"(v[i].y), "f"(v[i].z), "f"(v[i].w)
                         : "memory");
            if (l16 == 0) {
                if (ism[i]) {
                    atomicAdd(g_cntm + d[i], 1.0f);
                    atomicAdd(g_pos + d[i], __ldg(bitpos + base + i));
                } else {
                    atomicAdd(g_cntg + d[i], 1.0f);
                }
            }
        }
    }
}

// ---------------- K4: node MLP (neigh part precomputed) -> g_h ----------
// smem floats: w1f 0(4096) | w1pos 4096(64) | b1 4160(64) | w2 4224(8192) | b2 12416(128)
#define NODE_SMEM (12544 * 4)
__global__ void __launch_bounds__(256) k_node_all(
    const float* __restrict__ feat, const int* __restrict__ is_po,
    const float* __restrict__ nm_w1, const float* __restrict__ nm_b1,
    const float* __restrict__ nm_w2, const float* __restrict__ nm_b2,
    const float* __restrict__ ng_w1, const float* __restrict__ ng_b1,
    const float* __restrict__ ng_w2, const float* __restrict__ ng_b2)
{
    int nbm = (g_nm + 255) >> 8;
    bool MOD = (int)blockIdx.x < nbm;
    int tbase = (MOD ? blockIdx.x : blockIdx.x - nbm) * 256;
    int total = MOD ? g_nm : g_ng;
    if (tbase >= total) return;

    const float* w1 = MOD ? nm_w1 : ng_w1;
    const float* b1 = MOD ? nm_b1 : ng_b1;
    const float* w2 = MOD ? nm_w2 : ng_w2;
    const float* b2 = MOD ? nm_b2 : ng_b2;
    const float* w1f = w1 + (MOD ? 129 : 128) * 64;

    extern __shared__ float sm[];
    float* s_w1f = sm;
    float* s_w1pos = sm + 4096;
    float* s_b1 = sm + 4160;
    float* s_w2 = sm + 4224;
    float* s_b2 = sm + 12416;
    {
        int t = threadIdx.x;
        for (int i = t; i < 4096; i += 256) s_w1f[i] = w1f[i];
        for (int i = t; i < 64; i += 256) s_w1pos[i] = MOD ? w1[128 * 64 + i] : 0.f;
        for (int i = t; i < 64; i += 256) s_b1[i] = b1[i];
        for (int i = t; i < 8192; i += 256) s_w2[i] = w2[i];
        for (int i = t; i < 128; i += 256) s_b2[i] = b2[i];
    }
    __syncthreads();

    int t = tbase + threadIdx.x;
    if (t >= total) return;
    int nd = MOD ? g_perm_m[t] : g_perm_g[t];

    float cnt = MOD ? g_cntm[nd] : g_cntg[nd];
    float inv = 1.0f / fmaxf(cnt, 1.0f);
    const u64* srow = (const u64*)((MOD ? g_sum_m : g_sum_g) + (size_t)nd * 64);

    // hid = b1 + inv*sum (+ pos*w1pos) + feat@w1f
    u64 h2[32];
    {
        const u64* bp = (const u64*)s_b1;
        u64 iv = pack2(inv, inv);
#pragma unroll
        for (int i = 0; i < 32; i++) {
            u64 a = bp[i];
            fma2(a, iv, __ldg(srow + i));
            h2[i] = a;
        }
    }
    if (MOD) {
        float pos = g_pos[nd] * inv;
        l1in(h2, pos, s_w1pos);
    }
    {
        const float4* frow = (const float4*)(feat + (size_t)nd * 64);
#pragma unroll 2
        for (int k4 = 0; k4 < 16; k4++) {
            float4 v = __ldg(frow + k4);
            const float* wr = s_w1f + (k4 * 4) * 64;
            l1in(h2, v.x, wr);
            l1in(h2, v.y, wr + 64);
            l1in(h2, v.z, wr + 128);
            l1in(h2, v.w, wr + 192);
        }
    }
    leaky_pack(h2);

    bool keep = (__ldg(is_po + nd) != 1);
    float* orow = g_h + (size_t)nd * 128;
    u64 acc[16];
#pragma unroll 1
    for (int c = 0; c < 4; c++) {
        layer2_chunk<128>(h2, s_w2, s_b2, c * 32, acc);
        u64* op = (u64*)(orow + c * 32);
#pragma unroll
        for (int i = 0; i < 16; i++) {
            float a, b; unpack2(acc[i], a, b);
            if (keep) { a = fmaxf(a, 0.f); b = fmaxf(b, 0.f); }
            op[i] = pack2(a, b);
        }
    }
}

// ---------------- K5: readout, split by hidden-half (128 -> 64 + table -> partial)
// smem floats: w1h 0..8191 | A 8192 (65*66=4290) | B 12482 (4290) |
//              b1 16772(64) | w2 16836(64) | knots 16900(64) -> 16964 floats
#define SM_A 8192
#define SM_B 12482
#define SM_B1 16772
#define SM_W2 16836
#define SM_KN 16900
#define OUT_SMEM (16964 * 4)
__global__ void __launch_bounds__(256) k_out(
    const float* __restrict__ o_w1, const float* __restrict__ o_b1,
    const float* __restrict__ o_w2, const float* __restrict__ level,
    float* __restrict__ out, int n)
{
    int half = blockIdx.x & 1;
    int nb = blockIdx.x >> 1;

    extern __shared__ float sm[];
    for (int i = threadIdx.x; i < 8192; i += 256) {
        int row = i >> 6, col = i & 63;
        sm[i] = o_w1[row * 128 + half * 64 + col];
    }
    for (int i = threadIdx.x; i < 65 * 64; i += 256) {
        int seg = i >> 6, col = i & 63;
        sm[SM_A + seg * 66 + col] = g_A[seg * 128 + half * 64 + col];
        sm[SM_B + seg * 66 + col] = g_B[seg * 128 + half * 64 + col];
    }
    for (int i = threadIdx.x; i < 64; i += 256) {
        sm[SM_B1 + i] = o_b1[half * 64 + i];
        sm[SM_W2 + i] = o_w2[half * 64 + i];
        sm[SM_KN + i] = g_knots[i];
    }
    __syncthreads();

    int nd = nb * 256 + threadIdx.x;
    if (nd >= n) return;

    float lv = __ldg(level + nd);
    int s = 0;
#pragma unroll
    for (int k = 0; k < 64; k++) s += (sm[SM_KN + k] < lv) ? 1 : 0;

    u64 acc[32];
    {
        const float* Ar = sm + SM_A + s * 66;
        const float* Br = sm + SM_B + s * 66;
        const float* br = sm + SM_B1;
#pragma unroll
        for (int i = 0; i < 32; i++) {
            float a0 = fmaf(Ar[2 * i], lv, br[2 * i] + Br[2 * i]);
            float a1 = fmaf(Ar[2 * i + 1], lv, br[2 * i + 1] + Br[2 * i + 1]);
            acc[i] = pack2(a0, a1);
        }
    }
    const float4* xr = (const float4*)(g_h + (size_t)nd * 128);
#pragma unroll 2
    for (int k4 = 0; k4 < 32; k4++) {
        float4 v = __ldg(xr + k4);
        const float* wr = sm + (k4 * 4) * 64;
        l1in(acc, v.x, wr);
        l1in(acc, v.y, wr + 64);
        l1in(acc, v.z, wr + 128);
        l1in(acc, v.w, wr + 192);
    }
    float r = 0.f;
#pragma unroll
    for (int i = 0; i < 32; i++) {
        float a, b; unpack2(acc[i], a, b);
        r += leaky(a) * sm[SM_W2 + 2 * i] + leaky(b) * sm[SM_W2 + 2 * i + 1];
    }
    atomicAdd(out + nd, r);
}

// ---------------- host launch ----------------
extern "C" void kernel_launch(void* const* d_in, const int* in_sizes, int n_in,
                              void* d_out, int out_size)
{
    const float* feat    = (const float*)d_in[0];
    const float* pi_feat = (const float*)d_in[1];
    const float* level   = (const float*)d_in[2];
    const float* bitpos  = (const float*)d_in[3];

    const int *is_po, *is_module, *src_m, *dst_m, *src_g, *dst_g;
    const float *pi_w1, *pi_b1, *pi_w2, *pi_b2;
    const float *nm_w1, *nm_b1, *nm_w2, *nm_b2;
    const float *ng_w1, *ng_b1, *ng_w2, *ng_b2;
    const float *gw1, *gb1, *gw2, *gb2;
    const float *o_w1, *o_b1, *o_w2, *o_b2;
    int Em, Eg;

    if (in_sizes[4] < 1000) {
        // reference-signature order
        pi_w1 = (const float*)d_in[4];  pi_b1 = (const float*)d_in[5];
        pi_w2 = (const float*)d_in[6];  pi_b2 = (const float*)d_in[7];
        nm_w1 = (const float*)d_in[8];  nm_b1 = (const float*)d_in[9];
        nm_w2 = (const float*)d_in[10]; nm_b2 = (const float*)d_in[11];
        ng_w1 = (const float*)d_in[12]; ng_b1 = (const float*)d_in[13];
        ng_w2 = (const float*)d_in[14]; ng_b2 = (const float*)d_in[15];
        gw1 = (const float*)d_in[16];   gb1 = (const float*)d_in[17];
        gw2 = (const float*)d_in[18];   gb2 = (const float*)d_in[19];
        o_w1 = (const float*)d_in[20];  o_b1 = (const float*)d_in[21];
        o_w2 = (const float*)d_in[22];  o_b2 = (const float*)d_in[23];
        is_po = (const int*)d_in[24];   is_module = (const int*)d_in[25];
        src_m = (const int*)d_in[26];   dst_m = (const int*)d_in[27];
        src_g = (const int*)d_in[28];   dst_g = (const int*)d_in[29];
        Em = in_sizes[26]; Eg = in_sizes[28];
    } else {
        // setup_inputs dict order
        is_po = (const int*)d_in[4];    is_module = (const int*)d_in[5];
        src_m = (const int*)d_in[6];    dst_m = (const int*)d_in[7];
        src_g = (const int*)d_in[8];    dst_g = (const int*)d_in[9];
        pi_w1 = (const float*)d_in[10]; pi_b1 = (const float*)d_in[11];
        pi_w2 = (const float*)d_in[12]; pi_b2 = (const float*)d_in[13];
        nm_w1 = (const float*)d_in[14]; nm_b1 = (const float*)d_in[15];
        nm_w2 = (const float*)d_in[16]; nm_b2 = (const float*)d_in[17];
        ng_w1 = (const float*)d_in[18]; ng_b1 = (const float*)d_in[19];
        ng_w2 = (const float*)d_in[20]; ng_b2 = (const float*)d_in[21];
        gw1 = (const float*)d_in[22];   gb1 = (const float*)d_in[23];
        gw2 = (const float*)d_in[24];   gb2 = (const float*)d_in[25];
        o_w1 = (const float*)d_in[26];  o_b1 = (const float*)d_in[27];
        o_w2 = (const float*)d_in[28];  o_b2 = (const float*)d_in[29];
        Em = in_sizes[6]; Eg = in_sizes[8];
    }

    int n = in_sizes[2];  // level has N elements

    cudaFuncSetAttribute(k_pre, cudaFuncAttributeMaxDynamicSharedMemorySize, PRE_SMEM);
    cudaFuncSetAttribute(k_node_all, cudaFuncAttributeMaxDynamicSharedMemorySize, NODE_SMEM);
    cudaFuncSetAttribute(k_out, cudaFuncAttributeMaxDynamicSharedMemorySize, OUT_SMEM);

    int nb = (n + 255) / 256;

    // zero the (now 64-wide) sum buffers
    void* p_sum_m = nullptr; void* p_sum_g = nullptr;
    cudaGetSymbolAddress(&p_sum_m, g_sum_m);
    cudaGetSymbolAddress(&p_sum_g, g_sum_g);
    cudaMemsetAsync(p_sum_m, 0, (size_t)n * 64 * 4);
    cudaMemsetAsync(p_sum_g, 0, (size_t)n * 64 * 4);

    k_zero_small<<<nb, 256>>>(n);
    k_part<<<nb, 256>>>(is_module, n);
    k_compose<<<dim3(65, 2), 64>>>(pi_w2, pi_b2, nm_w1, ng_w1);
    k_table2<<<65, 128>>>(gw1, gb1, gw2, gb2, o_w1);

    k_pre<<<nb, 256, PRE_SMEM>>>(pi_feat, pi_w1, pi_b1, o_b2, (float*)d_out, n);

    long long Etot = (long long)Em + Eg;
    long long hws = (Etot + EPHW - 1) / EPHW;
    int eb = (int)((hws * 16 + 255) / 256);
    k_edges_all<<<eb, 256>>>(src_m, dst_m, src_g, dst_g, bitpos, Em, Eg);

    k_node_all<<<nb + 1, 256, NODE_SMEM>>>(
        feat, is_po,
        nm_w1, nm_b1, nm_w2, nm_b2,
        ng_w1, ng_b1, ng_w2, ng_b2);

    k_out<<<nb * 2, 256, OUT_SMEM>>>(o_w1, o_b1, o_w2, level, (float*)d_out, n);
}

// round 6
// speedup vs baseline: 2.5996x; 1.2216x over previous
#include <cuda_runtime.h>

#define NN 100000

typedef unsigned long long u64;

// ---------------- scratch (device globals) ----------------
__device__ float g_pm[(size_t)NN * 64];
__device__ float g_pg[(size_t)NN * 64];
__device__ float g_sum_m[(size_t)NN * 64];
__device__ float g_sum_g[(size_t)NN * 64];
__device__ float g_pos[NN];
__device__ float g_cntm[NN];
__device__ float g_cntg[NN];
__device__ float g_h[(size_t)NN * 128];
__device__ int   g_np[2];          // [0]=nm, [1]=ng
__device__ int   g_perm_m[NN];
__device__ int   g_perm_g[NN];
__device__ float g_Cm[65 * 64];
__device__ float g_Cg[65 * 64];
__device__ float g_A[65 * 128];
__device__ float g_B[65 * 128];
__device__ float g_knots[64];

__device__ __forceinline__ float leaky(float x) { return x > 0.f ? x : 0.1f * x; }

// ---- packed f32x2 helpers ----
__device__ __forceinline__ u64 pack2(float x, float y) {
    u64 r; asm("mov.b64 %0,{%1,%2};" : "=l"(r) : "f"(x), "f"(y)); return r;
}
__device__ __forceinline__ void unpack2(u64 v, float& x, float& y) {
    asm("mov.b64 {%0,%1},%2;" : "=f"(x), "=f"(y) : "l"(v));
}
__device__ __forceinline__ void fma2(u64& acc, u64 a, u64 b) {
    asm("fma.rn.f32x2 %0,%1,%2,%0;" : "+l"(acc) : "l"(a), "l"(b));
}

// one input feature per node (2 nodes) into 64-wide accumulators
__device__ __forceinline__ void l1in2(u64* ha, u64* hb, float xa_, float xb_,
                                      const float* w) {
    u64 xa = pack2(xa_, xa_), xb = pack2(xb_, xb_);
    const ulonglong2* wp = (const ulonglong2*)w;
#pragma unroll
    for (int i = 0; i < 16; i++) {
        ulonglong2 ww = wp[i];
        fma2(ha[2 * i], xa, ww.x);
        fma2(ha[2 * i + 1], xa, ww.y);
        fma2(hb[2 * i], xb, ww.x);
        fma2(hb[2 * i + 1], xb, ww.y);
    }
}

// 64 hidden (activated, packed) x 2 nodes -> 32 outputs at column j0 of [64,STRIDE]
template <int STRIDE>
__device__ __forceinline__ void layer2_chunk2(
    const u64* ha, const u64* hb, const float* w2, const float* b2, int j0,
    u64* aa, u64* ab)
{
    const u64* bp = (const u64*)(b2 + j0);
#pragma unroll
    for (int i = 0; i < 16; i++) { aa[i] = bp[i]; ab[i] = bp[i]; }
#pragma unroll 4
    for (int kk = 0; kk < 32; kk++) {
        float a0, a1, b0, b1;
        unpack2(ha[kk], a0, a1);
        unpack2(hb[kk], b0, b1);
        u64 xa0 = pack2(a0, a0), xa1 = pack2(a1, a1);
        u64 xb0 = pack2(b0, b0), xb1 = pack2(b1, b1);
        const ulonglong2* w0 = (const ulonglong2*)(w2 + (size_t)(2 * kk) * STRIDE + j0);
        const ulonglong2* w1 = (const ulonglong2*)(w2 + (size_t)(2 * kk + 1) * STRIDE + j0);
#pragma unroll
        for (int i = 0; i < 8; i++) {
            ulonglong2 w = w0[i];
            fma2(aa[2 * i], xa0, w.x); fma2(aa[2 * i + 1], xa0, w.y);
            fma2(ab[2 * i], xb0, w.x); fma2(ab[2 * i + 1], xb0, w.y);
        }
#pragma unroll
        for (int i = 0; i < 8; i++) {
            ulonglong2 w = w1[i];
            fma2(aa[2 * i], xa1, w.x); fma2(aa[2 * i + 1], xa1, w.y);
            fma2(ab[2 * i], xb1, w.x); fma2(ab[2 * i + 1], xb1, w.y);
        }
    }
}

__device__ __forceinline__ void leaky_pack(u64* h2) {
#pragma unroll
    for (int i = 0; i < 32; i++) {
        float a, b; unpack2(h2[i], a, b);
        h2[i] = pack2(leaky(a), leaky(b));
    }
}

// ---------------- K1: partition nodes by type + zero per-node scalars ----------
__global__ void k_part(const int* __restrict__ is_module, int n) {
    int i = blockIdx.x * blockDim.x + threadIdx.x;
    bool valid = i < n;
    if (valid) { g_pos[i] = 0.f; g_cntm[i] = 0.f; g_cntg[i] = 0.f; }
    bool m = valid && (is_module[i] == 1);
    bool g = valid && !m;
    unsigned bm = __ballot_sync(0xffffffffu, m);
    unsigned bg = __ballot_sync(0xffffffffu, g);
    int lane = threadIdx.x & 31;
    int base_m = 0, base_g = 0;
    if (lane == 0) {
        base_m = atomicAdd(&g_np[0], __popc(bm));
        base_g = atomicAdd(&g_np[1], __popc(bg));
    }
    base_m = __shfl_sync(0xffffffffu, base_m, 0);
    base_g = __shfl_sync(0xffffffffu, base_g, 0);
    unsigned lt = (1u << lane) - 1u;
    if (m) g_perm_m[base_m + __popc(bm & lt)] = i;
    if (g) g_perm_g[base_g + __popc(bg & lt)] = i;
}

// ---------------- KS: fused setup — compose (blocks 0..64) + table (65..129) ------
__global__ void k_setup(
    const float* __restrict__ piw2, const float* __restrict__ pib2,
    const float* __restrict__ nmw1, const float* __restrict__ ngw1,
    const float* __restrict__ gw1, const float* __restrict__ gb1,
    const float* __restrict__ gw2, const float* __restrict__ gb2,
    const float* __restrict__ o_w1)
{
    int b = blockIdx.x;
    if (b < 65) {
        // composed projections: C[i][j] = sum_c piw2[i][c]*W[c][j]; row 64 = pib2@W
        int i = b;
        int gsel = threadIdx.x >> 6;
        int j = threadIdx.x & 63;
        const float* W = gsel ? ngw1 : nmw1;
        const float* src = (i < 64) ? (piw2 + i * 128) : pib2;
        float acc = 0.f;
#pragma unroll 8
        for (int c = 0; c < 128; c++) acc += __ldg(src + c) * __ldg(W + c * 64 + j);
        (gsel ? g_Cg : g_Cm)[i * 64 + j] = acc;
        return;
    }
    // piecewise-linear table
    __shared__ float s_t[64], s_w[64], s_b[64];
    __shared__ int s_pos[64];
    __shared__ float s_a[128], s_c[128];
    int j = threadIdx.x;   // 0..127
    int s = b - 65;        // 0..64
    if (j < 64) {
        float w = gw1[j], bb = gb1[j];
        s_w[j] = w; s_b[j] = bb;
        s_t[j] = (w != 0.f) ? (-bb / w) : 3.0e38f;
    }
    __syncthreads();
    if (j < 64) {
        float t = s_t[j];
        int r = 0;
        for (int i = 0; i < 64; i++) {
            float ti = s_t[i];
            if (ti < t || (ti == t && i < j)) r++;
        }
        s_pos[j] = r;
    }
    __syncthreads();
    if (s == 0 && j < 64) g_knots[s_pos[j]] = s_t[j];

    {
        float a = 0.f, c = __ldg(gb2 + j);
#pragma unroll 8
        for (int k = 0; k < 64; k++) {
            float w = s_w[k], bb = s_b[k];
            bool positive = (w > 0.f) ? (s > s_pos[k])
                           : (w < 0.f) ? (s <= s_pos[k])
                           : (bb > 0.f);
            float sc = positive ? 1.0f : 0.1f;
            float gv = __ldg(gw2 + k * 128 + j);
            a += sc * w * gv;
            c += sc * bb * gv;
        }
        s_a[j] = a; s_c[j] = c;
    }
    __syncthreads();

    float A = 0.f, B = 0.f;
#pragma unroll 8
    for (int c = 0; c < 128; c++) {
        float o = __ldg(o_w1 + (size_t)(128 + c) * 128 + j);
        A += s_a[c] * o;
        B += s_c[c] * o;
    }
    g_A[s * 128 + j] = A;
    g_B[s * 128 + j] = B;
}

// ---------------- K2: hid_pi -> p_m, p_g (2 nodes per thread); seed out ------------
// smem: piw1 0(256) pib1 256(64) Cm 320(4160) Cg 4480(4160) tot 8640
#define PRE_SMEM (8640 * 4)
__global__ void __launch_bounds__(128) k_pre(
    const float* __restrict__ pi_feat,
    const float* __restrict__ piw1, const float* __restrict__ pib1,
    const float* __restrict__ o_b2, float* __restrict__ out, int n)
{
    extern __shared__ float sm[];
    {
        int t = threadIdx.x;
        for (int i = t; i < 256; i += 128) sm[i] = piw1[i];
        for (int i = t; i < 64; i += 128) sm[256 + i] = pib1[i];
        for (int i = t; i < 4160; i += 128) sm[320 + i] = g_Cm[i];
        for (int i = t; i < 4160; i += 128) sm[4480 + i] = g_Cg[i];
    }
    __syncthreads();

    int nd0 = blockIdx.x * 256 + threadIdx.x;
    if (nd0 >= n) return;
    int nd1 = nd0 + 128;
    bool v1 = nd1 < n;
    int nd1c = v1 ? nd1 : nd0;

    float ob2 = __ldg(o_b2);
    out[nd0] = ob2;
    if (v1) out[nd1] = ob2;

    float4 pa = __ldg((const float4*)pi_feat + nd0);
    float4 pb = __ldg((const float4*)pi_feat + nd1c);

    u64 ha[32], hb[32];
    {
        const u64* bp = (const u64*)(sm + 256);
#pragma unroll
        for (int i = 0; i < 32; i++) { ha[i] = bp[i]; hb[i] = bp[i]; }
        l1in2(ha, hb, pa.x, pb.x, sm + 0 * 64);
        l1in2(ha, hb, pa.y, pb.y, sm + 1 * 64);
        l1in2(ha, hb, pa.z, pb.z, sm + 2 * 64);
        l1in2(ha, hb, pa.w, pb.w, sm + 3 * 64);
        leaky_pack(ha);
        leaky_pack(hb);
    }
    u64 aa[16], ab[16];
#pragma unroll 1
    for (int c = 0; c < 2; c++) {
        layer2_chunk2<64>(ha, hb, sm + 320, sm + 320 + 64 * 64, c * 32, aa, ab);
        u64* oa = (u64*)(g_pm + (size_t)nd0 * 64 + c * 32);
        u64* ob = (u64*)(g_pm + (size_t)nd1 * 64 + c * 32);
#pragma unroll
        for (int i = 0; i < 16; i++) oa[i] = aa[i];
        if (v1) {
#pragma unroll
            for (int i = 0; i < 16; i++) ob[i] = ab[i];
        }
    }
#pragma unroll 1
    for (int c = 0; c < 2; c++) {
        layer2_chunk2<64>(ha, hb, sm + 4480, sm + 4480 + 64 * 64, c * 32, aa, ab);
        u64* oa = (u64*)(g_pg + (size_t)nd0 * 64 + c * 32);
        u64* ob = (u64*)(g_pg + (size_t)nd1 * 64 + c * 32);
#pragma unroll
        for (int i = 0; i < 16; i++) oa[i] = aa[i];
        if (v1) {
#pragma unroll
            for (int i = 0; i < 16; i++) ob[i] = ab[i];
        }
    }
}

// ---------------- K3: edge gather + reduction, half-warp per edge, 64-dim ----------
#define EPHW 4
__global__ void __launch_bounds__(256) k_edges_all(
    const int* __restrict__ src_m, const int* __restrict__ dst_m,
    const int* __restrict__ src_g, const int* __restrict__ dst_g,
    const float* __restrict__ bitpos, int Em, int Eg)
{
    int l16 = threadIdx.x & 15;
    long long hw = ((long long)blockIdx.x * blockDim.x + threadIdx.x) >> 4;
    long long base = hw * EPHW;
    long long Etot = (long long)Em + Eg;
    if (base >= Etot) return;
    int cnt = (int)(Etot - base < EPHW ? Etot - base : EPHW);

    int s[EPHW], d[EPHW];
    bool ism[EPHW];
#pragma unroll
    for (int i = 0; i < EPHW; i++) {
        if (i < cnt) {
            long long e = base + i;
            if (e < Em) {
                ism[i] = true;
                s[i] = __ldg(src_m + e);
                d[i] = __ldg(dst_m + e);
            } else {
                ism[i] = false;
                s[i] = __ldg(src_g + (e - Em));
                d[i] = __ldg(dst_g + (e - Em));
            }
        }
    }
    float4 v[EPHW];
#pragma unroll
    for (int i = 0; i < EPHW; i++)
        if (i < cnt)
            v[i] = __ldg((const float4*)((ism[i] ? g_pm : g_pg) + (size_t)s[i] * 64) + l16);
#pragma unroll
    for (int i = 0; i < EPHW; i++) {
        if (i < cnt) {
            float* p = (ism[i] ? g_sum_m : g_sum_g) + (size_t)d[i] * 64 + l16 * 4;
            asm volatile("red.global.add.v4.f32 [%0], {%1,%2,%3,%4};"
                         :: "l"(p), "f"(v[i].x), "f"(v[i].y), "f"(v[i].z), "f"(v[i].w)
                         : "memory");
            if (l16 == 0) {
                if (ism[i]) {
                    atomicAdd(g_cntm + d[i], 1.0f);
                    atomicAdd(g_pos + d[i], __ldg(bitpos + base + i));
                } else {
                    atomicAdd(g_cntg + d[i], 1.0f);
                }
            }
        }
    }
}

// ---------------- K4: node MLP, 2 nodes/thread -> g_h ----------
// smem floats: w1f 0(4096) | w1pos 4096(64) | b1 4160(64) | w2 4224(8192) | b2 12416(128)
#define NODE_SMEM (12544 * 4)
__global__ void __launch_bounds__(128) k_node_all(
    const float* __restrict__ feat, const int* __restrict__ is_po,
    const float* __restrict__ nm_w1, const float* __restrict__ nm_b1,
    const float* __restrict__ nm_w2, const float* __restrict__ nm_b2,
    const float* __restrict__ ng_w1, const float* __restrict__ ng_b1,
    const float* __restrict__ ng_w2, const float* __restrict__ ng_b2)
{
    int nm = g_np[0], ng = g_np[1];
    int nbm = (nm + 255) >> 8;
    bool MOD = (int)blockIdx.x < nbm;
    int tbase = (MOD ? blockIdx.x : blockIdx.x - nbm) * 256;
    int total = MOD ? nm : ng;
    if (tbase >= total) return;

    const float* w1 = MOD ? nm_w1 : ng_w1;
    const float* b1 = MOD ? nm_b1 : ng_b1;
    const float* w2 = MOD ? nm_w2 : ng_w2;
    const float* b2 = MOD ? nm_b2 : ng_b2;
    const float* w1f = w1 + (MOD ? 129 : 128) * 64;
    const int* perm = MOD ? g_perm_m : g_perm_g;
    const float* sums = MOD ? g_sum_m : g_sum_g;
    const float* cnts = MOD ? g_cntm : g_cntg;

    extern __shared__ float sm[];
    float* s_w1f = sm;
    float* s_w1pos = sm + 4096;
    float* s_b1 = sm + 4160;
    float* s_w2 = sm + 4224;
    float* s_b2 = sm + 12416;
    {
        int t = threadIdx.x;
        for (int i = t; i < 4096; i += 128) s_w1f[i] = w1f[i];
        for (int i = t; i < 64; i += 128) s_w1pos[i] = MOD ? w1[128 * 64 + i] : 0.f;
        for (int i = t; i < 64; i += 128) s_b1[i] = b1[i];
        for (int i = t; i < 8192; i += 128) s_w2[i] = w2[i];
        for (int i = t; i < 128; i += 128) s_b2[i] = b2[i];
    }
    __syncthreads();

    int t0 = tbase + threadIdx.x;
    if (t0 >= total) return;
    int t1 = t0 + 128;
    bool v1 = t1 < total;
    int nda = perm[t0];
    int ndb = v1 ? perm[t1] : nda;

    float inva = 1.0f / fmaxf(cnts[nda], 1.0f);
    float invb = 1.0f / fmaxf(cnts[ndb], 1.0f);
    const u64* sra = (const u64*)(sums + (size_t)nda * 64);
    const u64* srb = (const u64*)(sums + (size_t)ndb * 64);

    u64 ha[32], hb[32];
    {
        const u64* bp = (const u64*)s_b1;
        u64 iva = pack2(inva, inva), ivb = pack2(invb, invb);
#pragma unroll
        for (int i = 0; i < 32; i++) {
            u64 a = bp[i], b = bp[i];
            fma2(a, iva, __ldg(sra + i));
            fma2(b, ivb, __ldg(srb + i));
            ha[i] = a; hb[i] = b;
        }
    }
    if (MOD) {
        float posa = g_pos[nda] * inva;
        float posb = g_pos[ndb] * invb;
        l1in2(ha, hb, posa, posb, s_w1pos);
    }
    {
        const float4* fa = (const float4*)(feat + (size_t)nda * 64);
        const float4* fb = (const float4*)(feat + (size_t)ndb * 64);
#pragma unroll 2
        for (int k4 = 0; k4 < 16; k4++) {
            float4 va = __ldg(fa + k4);
            float4 vb = __ldg(fb + k4);
            const float* wr = s_w1f + (k4 * 4) * 64;
            l1in2(ha, hb, va.x, vb.x, wr);
            l1in2(ha, hb, va.y, vb.y, wr + 64);
            l1in2(ha, hb, va.z, vb.z, wr + 128);
            l1in2(ha, hb, va.w, vb.w, wr + 192);
        }
    }
    leaky_pack(ha);
    leaky_pack(hb);

    bool keepa = (__ldg(is_po + nda) != 1);
    bool keepb = (__ldg(is_po + ndb) != 1);
    float* ora = g_h + (size_t)nda * 128;
    float* orb = g_h + (size_t)ndb * 128;
    u64 aa[16], ab[16];
#pragma unroll 1
    for (int c = 0; c < 4; c++) {
        layer2_chunk2<128>(ha, hb, s_w2, s_b2, c * 32, aa, ab);
        u64* oa = (u64*)(ora + c * 32);
#pragma unroll
        for (int i = 0; i < 16; i++) {
            float x, y; unpack2(aa[i], x, y);
            if (keepa) { x = fmaxf(x, 0.f); y = fmaxf(y, 0.f); }
            oa[i] = pack2(x, y);
        }
        if (v1) {
            u64* ob = (u64*)(orb + c * 32);
#pragma unroll
            for (int i = 0; i < 16; i++) {
                float x, y; unpack2(ab[i], x, y);
                if (keepb) { x = fmaxf(x, 0.f); y = fmaxf(y, 0.f); }
                ob[i] = pack2(x, y);
            }
        }
    }
}

// ---------------- K5: readout, hidden-half split, 2 nodes/thread ----------------
// smem floats: w1h 0..8191 | A 8192 (65*66=4290) | B 12482 (4290) |
//              b1 16772(64) | w2 16836(64) | knots 16900(64) -> 16964 floats
#define SM_A 8192
#define SM_B 12482
#define SM_B1 16772
#define SM_W2 16836
#define SM_KN 16900
#define OUT_SMEM (16964 * 4)
__global__ void __launch_bounds__(128) k_out(
    const float* __restrict__ o_w1, const float* __restrict__ o_b1,
    const float* __restrict__ o_w2, const float* __restrict__ level,
    float* __restrict__ out, int n)
{
    int half = blockIdx.x & 1;
    int nb = blockIdx.x >> 1;

    extern __shared__ float sm[];
    for (int i = threadIdx.x; i < 8192; i += 128) {
        int row = i >> 6, col = i & 63;
        sm[i] = o_w1[row * 128 + half * 64 + col];
    }
    for (int i = threadIdx.x; i < 65 * 64; i += 128) {
        int seg = i >> 6, col = i & 63;
        sm[SM_A + seg * 66 + col] = g_A[seg * 128 + half * 64 + col];
        sm[SM_B + seg * 66 + col] = g_B[seg * 128 + half * 64 + col];
    }
    for (int i = threadIdx.x; i < 64; i += 128) {
        sm[SM_B1 + i] = o_b1[half * 64 + i];
        sm[SM_W2 + i] = o_w2[half * 64 + i];
        sm[SM_KN + i] = g_knots[i];
    }
    __syncthreads();

    int nd0 = nb * 256 + threadIdx.x;
    if (nd0 >= n) return;
    int nd1 = nd0 + 128;
    bool v1 = nd1 < n;
    int nd1c = v1 ? nd1 : nd0;

    float lva = __ldg(level + nd0);
    float lvb = __ldg(level + nd1c);
    int sa = 0, sb = 0;
#pragma unroll
    for (int k = 0; k < 64; k++) {
        float kn = sm[SM_KN + k];
        sa += (kn < lva) ? 1 : 0;
        sb += (kn < lvb) ? 1 : 0;
    }

    u64 aa[32], ab[32];
    {
        const float* Aa = sm + SM_A + sa * 66;
        const float* Ba = sm + SM_B + sa * 66;
        const float* Ab = sm + SM_A + sb * 66;
        const float* Bb = sm + SM_B + sb * 66;
        const float* br = sm + SM_B1;
#pragma unroll
        for (int i = 0; i < 32; i++) {
            float a0 = fmaf(Aa[2 * i], lva, br[2 * i] + Ba[2 * i]);
            float a1 = fmaf(Aa[2 * i + 1], lva, br[2 * i + 1] + Ba[2 * i + 1]);
            aa[i] = pack2(a0, a1);
            float b0 = fmaf(Ab[2 * i], lvb, br[2 * i] + Bb[2 * i]);
            float b1 = fmaf(Ab[2 * i + 1], lvb, br[2 * i + 1] + Bb[2 * i + 1]);
            ab[i] = pack2(b0, b1);
        }
    }
    const float4* xa = (const float4*)(g_h + (size_t)nd0 * 128);
    const float4* xb = (const float4*)(g_h + (size_t)nd1c * 128);
#pragma unroll 2
    for (int k4 = 0; k4 < 32; k4++) {
        float4 va = __ldg(xa + k4);
        float4 vb = __ldg(xb + k4);
        const float* wr = sm + (k4 * 4) * 64;
        l1in2(aa, ab, va.x, vb.x, wr);
        l1in2(aa, ab, va.y, vb.y, wr + 64);
        l1in2(aa, ab, va.z, vb.z, wr + 128);
        l1in2(aa, ab, va.w, vb.w, wr + 192);
    }
    float ra = 0.f, rb = 0.f;
#pragma unroll
    for (int i = 0; i < 32; i++) {
        float x, y; unpack2(aa[i], x, y);
        ra += leaky(x) * sm[SM_W2 + 2 * i] + leaky(y) * sm[SM_W2 + 2 * i + 1];
        unpack2(ab[i], x, y);
        rb += leaky(x) * sm[SM_W2 + 2 * i] + leaky(y) * sm[SM_W2 + 2 * i + 1];
    }
    atomicAdd(out + nd0, ra);
    if (v1) atomicAdd(out + nd1, rb);
}

// ---------------- host launch ----------------
extern "C" void kernel_launch(void* const* d_in, const int* in_sizes, int n_in,
                              void* d_out, int out_size)
{
    const float* feat    = (const float*)d_in[0];
    const float* pi_feat = (const float*)d_in[1];
    const float* level   = (const float*)d_in[2];
    const float* bitpos  = (const float*)d_in[3];

    const int *is_po, *is_module, *src_m, *dst_m, *src_g, *dst_g;
    const float *pi_w1, *pi_b1, *pi_w2, *pi_b2;
    const float *nm_w1, *nm_b1, *nm_w2, *nm_b2;
    const float *ng_w1, *ng_b1, *ng_w2, *ng_b2;
    const float *gw1, *gb1, *gw2, *gb2;
    const float *o_w1, *o_b1, *o_w2, *o_b2;
    int Em, Eg;

    if (in_sizes[4] < 1000) {
        // reference-signature order
        pi_w1 = (const float*)d_in[4];  pi_b1 = (const float*)d_in[5];
        pi_w2 = (const float*)d_in[6];  pi_b2 = (const float*)d_in[7];
        nm_w1 = (const float*)d_in[8];  nm_b1 = (const float*)d_in[9];
        nm_w2 = (const float*)d_in[10]; nm_b2 = (const float*)d_in[11];
        ng_w1 = (const float*)d_in[12]; ng_b1 = (const float*)d_in[13];
        ng_w2 = (const float*)d_in[14]; ng_b2 = (const float*)d_in[15];
        gw1 = (const float*)d_in[16];   gb1 = (const float*)d_in[17];
        gw2 = (const float*)d_in[18];   gb2 = (const float*)d_in[19];
        o_w1 = (const float*)d_in[20];  o_b1 = (const float*)d_in[21];
        o_w2 = (const float*)d_in[22];  o_b2 = (const float*)d_in[23];
        is_po = (const int*)d_in[24];   is_module = (const int*)d_in[25];
        src_m = (const int*)d_in[26];   dst_m = (const int*)d_in[27];
        src_g = (const int*)d_in[28];   dst_g = (const int*)d_in[29];
        Em = in_sizes[26]; Eg = in_sizes[28];
    } else {
        // setup_inputs dict order
        is_po = (const int*)d_in[4];    is_module = (const int*)d_in[5];
        src_m = (const int*)d_in[6];    dst_m = (const int*)d_in[7];
        src_g = (const int*)d_in[8];    dst_g = (const int*)d_in[9];
        pi_w1 = (const float*)d_in[10]; pi_b1 = (const float*)d_in[11];
        pi_w2 = (const float*)d_in[12]; pi_b2 = (const float*)d_in[13];
        nm_w1 = (const float*)d_in[14]; nm_b1 = (const float*)d_in[15];
        nm_w2 = (const float*)d_in[16]; nm_b2 = (const float*)d_in[17];
        ng_w1 = (const float*)d_in[18]; ng_b1 = (const float*)d_in[19];
        ng_w2 = (const float*)d_in[20]; ng_b2 = (const float*)d_in[21];
        gw1 = (const float*)d_in[22];   gb1 = (const float*)d_in[23];
        gw2 = (const float*)d_in[24];   gb2 = (const float*)d_in[25];
        o_w1 = (const float*)d_in[26];  o_b1 = (const float*)d_in[27];
        o_w2 = (const float*)d_in[28];  o_b2 = (const float*)d_in[29];
        Em = in_sizes[6]; Eg = in_sizes[8];
    }

    int n = in_sizes[2];  // level has N elements

    cudaFuncSetAttribute(k_pre, cudaFuncAttributeMaxDynamicSharedMemorySize, PRE_SMEM);
    cudaFuncSetAttribute(k_node_all, cudaFuncAttributeMaxDynamicSharedMemorySize, NODE_SMEM);
    cudaFuncSetAttribute(k_out, cudaFuncAttributeMaxDynamicSharedMemorySize, OUT_SMEM);

    int nb = (n + 255) / 256;     // 128 threads x 2 nodes
    int nbp = (n + 255) / 256;    // k_part blocks (256 threads)

    void* p = nullptr;
    cudaGetSymbolAddress(&p, g_sum_m);
    cudaMemsetAsync(p, 0, (size_t)n * 64 * 4);
    cudaGetSymbolAddress(&p, g_sum_g);
    cudaMemsetAsync(p, 0, (size_t)n * 64 * 4);
    cudaGetSymbolAddress(&p, g_np);
    cudaMemsetAsync(p, 0, 8);

    k_part<<<nbp, 256>>>(is_module, n);
    k_setup<<<130, 128>>>(pi_w2, pi_b2, nm_w1, ng_w1, gw1, gb1, gw2, gb2, o_w1);

    k_pre<<<nb, 128, PRE_SMEM>>>(pi_feat, pi_w1, pi_b1, o_b2, (float*)d_out, n);

    long long Etot = (long long)Em + Eg;
    long long hws = (Etot + EPHW - 1) / EPHW;
    int eb = (int)((hws * 16 + 255) / 256);
    k_edges_all<<<eb, 256>>>(src_m, dst_m, src_g, dst_g, bitpos, Em, Eg);

    k_node_all<<<nb + 1, 128, NODE_SMEM>>>(
        feat, is_po,
        nm_w1, nm_b1, nm_w2, nm_b2,
        ng_w1, ng_b1, ng_w2, ng_b2);

    k_out<<<nb * 2, 128, OUT_SMEM>>>(o_w1, o_b1, o_w2, level, (float*)d_out, n);
}